// round 4
// baseline (speedup 1.0000x reference)
#include <cuda_runtime.h>
#include <cuda_bf16.h>
#include <cstddef>
#include <cstdint>

#define BATCH 2
#define NPTS  8192
#define DIM   64
#define KNN   16
#define NPOINTS_TOTAL (BATCH * NPTS)

// tf32 operand rounding for the K=64 GEMMs (cublas tf32 path emulation).
__device__ __forceinline__ float tf32r(float x) {
    uint32_t y;
    asm("cvt.rna.tf32.f32 %0, %1;" : "=r"(y) : "f"(x));
    return __uint_as_float(y);
}

// ---------------- scratch (static device globals; no runtime allocation) ----
__device__ float g_xq[NPOINTS_TOTAL * DIM];
__device__ float g_xk[NPOINTS_TOTAL * DIM];
__device__ float g_xv[NPOINTS_TOTAL * DIM];
__device__ int   g_idx[NPOINTS_TOTAL * KNN];

// ============================================================================
// KNN kernel: one warp per query. FP32 exact distances (reference's K=3 einsum
// is an elementwise fp32 lowering, NOT tf32). No fma in the 3-term dot.
// ============================================================================
__global__ void __launch_bounds__(256) knn_kernel(const float* __restrict__ pos) {
    const int b    = blockIdx.x >> 10;     // 1024 blocks per batch
    const int blk  = blockIdx.x & 1023;
    const int wid  = threadIdx.x >> 5;
    const int lane = threadIdx.x & 31;
    const int n    = blk * 8 + wid;        // query index within batch

    const float* posb = pos + (size_t)b * NPTS * 3;
    __shared__ float4 tile[1024];          // (x, y, z, sq) all fp32

    const float qx = posb[n * 3 + 0];
    const float qy = posb[n * 3 + 1];
    const float qz = posb[n * 3 + 2];
    // sq fp32, XLA elementwise order: ((x*x + y*y) + z*z), no fma
    const float sqq = __fadd_rn(__fadd_rn(__fmul_rn(qx, qx), __fmul_rn(qy, qy)),
                                __fmul_rn(qz, qz));

    float bd[16];
    int   bi[16];
#pragma unroll
    for (int i = 0; i < 16; i++) { bd[i] = 1e30f; bi[i] = 0x7fffffff; }
    float worst = 1e30f;
    int   worstid = 0x7fffffff;
    int   worstslot = 0;

    for (int base = 0; base < NPTS; base += 1024) {
        __syncthreads();
        for (int t = threadIdx.x; t < 1024; t += 256) {
            const int j = base + t;
            const float px = posb[j * 3 + 0];
            const float py = posb[j * 3 + 1];
            const float pz = posb[j * 3 + 2];
            const float sq = __fadd_rn(__fadd_rn(__fmul_rn(px, px), __fmul_rn(py, py)),
                                       __fmul_rn(pz, pz));
            tile[t] = make_float4(px, py, pz, sq);
        }
        __syncthreads();

        for (int t = lane; t < 1024; t += 32) {
            const float4 p = tile[t];
            // fp32, mul then sequential add (elementwise-lowering order; no fma)
            const float dot = __fadd_rn(__fadd_rn(__fmul_rn(qx, p.x), __fmul_rn(qy, p.y)),
                                        __fmul_rn(qz, p.z));
            // (sq_i + sq_j) - 2*dot, fp32, XLA fusion order
            const float d2 = __fsub_rn(__fadd_rn(sqq, p.w), __fmul_rn(2.0f, dot));
            const int   j  = base + t;
            if (d2 < worst || (d2 == worst && j < worstid)) {
#pragma unroll
                for (int i = 0; i < 16; i++)
                    if (i == worstslot) { bd[i] = d2; bi[i] = j; }
                worst = bd[0]; worstid = bi[0]; worstslot = 0;
#pragma unroll
                for (int i = 1; i < 16; i++) {
                    const bool g = (bd[i] > worst) || (bd[i] == worst && bi[i] > worstid);
                    if (g) { worst = bd[i]; worstid = bi[i]; worstslot = i; }
                }
            }
        }
    }

    // Bitonic sort the local 16 ascending by (d2, idx)
#pragma unroll
    for (int sz = 2; sz <= 16; sz <<= 1) {
#pragma unroll
        for (int st = sz >> 1; st > 0; st >>= 1) {
#pragma unroll
            for (int i = 0; i < 16; i++) {
                const int j = i ^ st;
                if (j > i) {
                    const bool up = ((i & sz) == 0);
                    const bool gt = (bd[i] > bd[j]) || (bd[i] == bd[j] && bi[i] > bi[j]);
                    if (gt == up) {
                        const float td = bd[i]; bd[i] = bd[j]; bd[j] = td;
                        const int   ti = bi[i]; bi[i] = bi[j]; bi[j] = ti;
                    }
                }
            }
        }
    }

    // Warp merge: 16 rounds of argmin over lane heads
    const int outbase = ((b << 13) + n) * KNN;
#pragma unroll 1
    for (int r = 0; r < 16; r++) {
        float v  = bd[0];
        int   vid = bi[0];
#pragma unroll
        for (int off = 16; off > 0; off >>= 1) {
            const float ov  = __shfl_xor_sync(0xffffffffu, v, off);
            const int   oid = __shfl_xor_sync(0xffffffffu, vid, off);
            if (ov < v || (ov == v && oid < vid)) { v = ov; vid = oid; }
        }
        if (lane == 0) g_idx[outbase + r] = vid;
        if (vid == bi[0]) {
#pragma unroll
            for (int i = 0; i < 15; i++) { bd[i] = bd[i + 1]; bi[i] = bi[i + 1]; }
            bd[15] = 1e30f; bi[15] = 0x7fffffff;
        }
    }
}

// ============================================================================
// Projection kernel: xq = x@Wq, xk = x@Wk, xv = x@Wv  (tf32 operands, K=64)
// ============================================================================
struct ProjSmem {
    float WqT[64 * 68];
    float WkT[64 * 68];
    float WvT[64 * 68];
    float xs[16 * 68];
};

__global__ void __launch_bounds__(1024) proj_kernel(const float* __restrict__ x,
                                                    const float* __restrict__ Wq,
                                                    const float* __restrict__ Wk,
                                                    const float* __restrict__ Wv) {
    extern __shared__ __align__(16) unsigned char proj_raw[];
    ProjSmem* S = reinterpret_cast<ProjSmem*>(proj_raw);

    const int tid = threadIdx.x;
    const int r = tid >> 6;
    const int d = tid & 63;

    for (int e = tid; e < 4096; e += 1024) {
        const int i = e >> 6, c = e & 63;
        S->WqT[c * 68 + i] = tf32r(Wq[e]);
        S->WkT[c * 68 + i] = tf32r(Wk[e]);
        S->WvT[c * 68 + i] = tf32r(Wv[e]);
    }
    const size_t rowbase = (size_t)blockIdx.x * 16;
    for (int e = tid; e < 16 * 64; e += 1024) {
        const int rr = e >> 6, c = e & 63;
        S->xs[rr * 68 + c] = tf32r(x[(rowbase + rr) * 64 + c]);
    }
    __syncthreads();

    const float4* xv4 = (const float4*)(S->xs + r * 68);
    const float4* wq4 = (const float4*)(S->WqT + d * 68);
    const float4* wk4 = (const float4*)(S->WkT + d * 68);
    const float4* wv4 = (const float4*)(S->WvT + d * 68);
    float aq = 0.f, ak = 0.f, av = 0.f;
#pragma unroll
    for (int i = 0; i < 16; i++) {
        const float4 xv = xv4[i];
        const float4 wq = wq4[i];
        const float4 wk = wk4[i];
        const float4 wv = wv4[i];
        aq = fmaf(wq.x, xv.x, aq); aq = fmaf(wq.y, xv.y, aq);
        aq = fmaf(wq.z, xv.z, aq); aq = fmaf(wq.w, xv.w, aq);
        ak = fmaf(wk.x, xv.x, ak); ak = fmaf(wk.y, xv.y, ak);
        ak = fmaf(wk.z, xv.z, ak); ak = fmaf(wk.w, xv.w, ak);
        av = fmaf(wv.x, xv.x, av); av = fmaf(wv.y, xv.y, av);
        av = fmaf(wv.z, xv.z, av); av = fmaf(wv.w, xv.w, av);
    }
    const size_t o = (rowbase + r) * 64 + d;
    g_xq[o] = aq; g_xk[o] = ak; g_xv[o] = av;
}

// ============================================================================
// Fused per-point attention kernel. One 1024-thread block per point.
// thread = (kk = neighbor 0..15, d = dim 0..63).
// K=64 GEMM operands tf32; K=3 contraction (rel@P1) fp32 elementwise order.
// ============================================================================
struct AttnSmem {
    float P2T[64 * 68];
    float A1T[64 * 68];
    float A2T[64 * 68];
    float WfT[64 * 68];
    float P1s[3 * 64];
    float pb1s[64], pb2s[64], ab1s[64], ab2s[64], bfs[64];
    float qs[64];
    float posn[4];
    float kt[16 * 64];
    float vt[16 * 64];
    float rel[16 * 4];
    float hidT[16 * 68];
    float hT[16 * 68];
    float tT[16 * 68];
    float abuf[16 * 64];
    float agg[64];
};

__global__ void __launch_bounds__(1024) attn_kernel(const float* __restrict__ x,
                                                    const float* __restrict__ pos,
                                                    const float* __restrict__ P1,
                                                    const float* __restrict__ pb1,
                                                    const float* __restrict__ P2,
                                                    const float* __restrict__ pb2,
                                                    const float* __restrict__ A1,
                                                    const float* __restrict__ ab1,
                                                    const float* __restrict__ A2,
                                                    const float* __restrict__ ab2,
                                                    const float* __restrict__ Wf,
                                                    const float* __restrict__ bf,
                                                    float* __restrict__ out) {
    extern __shared__ __align__(16) unsigned char attn_raw[];
    AttnSmem* S = reinterpret_cast<AttnSmem*>(attn_raw);

    const int tid = threadIdx.x;
    const int kk  = tid >> 6;
    const int d   = tid & 63;
    const int pnt = blockIdx.x;         // 0..16383
    const int b   = pnt >> 13;
    const int n   = pnt & 8191;

    // stage weights transposed; tf32 round the K=64 GEMM weights
    for (int e = tid; e < 4096; e += 1024) {
        const int i = e >> 6, c = e & 63;
        S->P2T[c * 68 + i] = tf32r(P2[e]);
        S->A1T[c * 68 + i] = tf32r(A1[e]);
        S->A2T[c * 68 + i] = tf32r(A2[e]);
        S->WfT[c * 68 + i] = tf32r(Wf[e]);
    }
    if (tid < 192) S->P1s[tid] = P1[tid];    // fp32 (K=3 elementwise path)
    if (tid < 64) {
        S->pb1s[tid] = pb1[tid];
        S->pb2s[tid] = pb2[tid];
        S->ab1s[tid] = ab1[tid];
        S->ab2s[tid] = ab2[tid];
        S->bfs[tid]  = bf[tid];
        S->qs[tid]   = g_xq[(size_t)pnt * 64 + tid];
    }
    if (tid < 3) S->posn[tid] = pos[((size_t)b * NPTS + n) * 3 + tid];

    const int nb = g_idx[pnt * KNN + kk];
    S->kt[kk * 64 + d] = g_xk[((size_t)b * NPTS + nb) * 64 + d];
    S->vt[kk * 64 + d] = g_xv[((size_t)b * NPTS + nb) * 64 + d];
    __syncthreads();

    if (d < 3) S->rel[kk * 4 + d] = S->posn[d] - pos[((size_t)b * NPTS + nb) * 3 + d];
    __syncthreads();

    // hidden = relu(rel @ P1 + pb1) -- fp32, mul + sequential add, then + bias
    const float r0 = S->rel[kk * 4 + 0];
    const float r1 = S->rel[kk * 4 + 1];
    const float r2 = S->rel[kk * 4 + 2];
    const float dotp = __fadd_rn(__fadd_rn(__fmul_rn(r0, S->P1s[d]),
                                           __fmul_rn(r1, S->P1s[64 + d])),
                                 __fmul_rn(r2, S->P1s[128 + d]));
    const float hd = __fadd_rn(dotp, S->pb1s[d]);
    S->hidT[kk * 68 + d] = tf32r(fmaxf(hd, 0.f));   // operand of P2 (tf32) gemm
    __syncthreads();

    // pe = hidden @ P2 + pb2  (tf32 operands, fp32 accumulate)
    float pe = S->pb2s[d];
    {
        const float4* w4 = (const float4*)(S->P2T + d * 68);
        const float4* h4 = (const float4*)(S->hidT + kk * 68);
#pragma unroll
        for (int i = 0; i < 16; i++) {
            const float4 w = w4[i];
            const float4 h = h4[i];
            pe = fmaf(w.x, h.x, pe); pe = fmaf(w.y, h.y, pe);
            pe = fmaf(w.z, h.z, pe); pe = fmaf(w.w, h.w, pe);
        }
    }
    // h = q - k + pe (elementwise fp32), stored tf32 as A1 operand
    S->hT[kk * 68 + d] = tf32r(S->qs[d] - S->kt[kk * 64 + d] + pe);
    __syncthreads();

    // t = relu(h @ A1 + ab1)
    float t = S->ab1s[d];
    {
        const float4* w4 = (const float4*)(S->A1T + d * 68);
        const float4* h4 = (const float4*)(S->hT + kk * 68);
#pragma unroll
        for (int i = 0; i < 16; i++) {
            const float4 w = w4[i];
            const float4 h = h4[i];
            t = fmaf(w.x, h.x, t); t = fmaf(w.y, h.y, t);
            t = fmaf(w.z, h.z, t); t = fmaf(w.w, h.w, t);
        }
    }
    S->tT[kk * 68 + d] = tf32r(fmaxf(t, 0.f));      // operand of A2 (tf32) gemm
    __syncthreads();

    // a = t @ A2 + ab2
    float a = S->ab2s[d];
    {
        const float4* w4 = (const float4*)(S->A2T + d * 68);
        const float4* h4 = (const float4*)(S->tT + kk * 68);
#pragma unroll
        for (int i = 0; i < 16; i++) {
            const float4 w = w4[i];
            const float4 h = h4[i];
            a = fmaf(w.x, h.x, a); a = fmaf(w.y, h.y, a);
            a = fmaf(w.z, h.z, a); a = fmaf(w.w, h.w, a);
        }
    }
    S->abuf[kk * 64 + d] = a;
    __syncthreads();

    // softmax over neighbors (axis k), scale 1/sqrt(64) -- fp32
    float m = -1e30f;
#pragma unroll
    for (int j = 0; j < 16; j++) m = fmaxf(m, S->abuf[j * 64 + d]);
    const float e = __expf((a - m) * 0.125f);
    __syncthreads();
    S->abuf[kk * 64 + d] = e;
    __syncthreads();
    float s = 0.f;
#pragma unroll
    for (int j = 0; j < 16; j++) s += S->abuf[j * 64 + d];
    const float attn = e / s;
    const float contrib = attn * (S->vt[kk * 64 + d] + pe);   // fp32 mul-reduce
    __syncthreads();
    S->abuf[kk * 64 + d] = contrib;
    __syncthreads();

    if (kk == 0) {
        float ag = 0.f;
#pragma unroll
        for (int j = 0; j < 16; j++) ag += S->abuf[j * 64 + d];
        S->agg[d] = tf32r(ag);       // operand of Wf (tf32) gemm
    }
    __syncthreads();

    if (kk == 0) {
        float o = S->bfs[d] + x[(size_t)pnt * 64 + d];
        const float4* w4 = (const float4*)(S->WfT + d * 68);
        const float4* g4 = (const float4*)(S->agg);
#pragma unroll
        for (int i = 0; i < 16; i++) {
            const float4 w = w4[i];
            const float4 g = g4[i];
            o = fmaf(w.x, g.x, o); o = fmaf(w.y, g.y, o);
            o = fmaf(w.z, g.z, o); o = fmaf(w.w, g.w, o);
        }
        out[(size_t)pnt * 64 + d] = o;
    }
}

// ============================================================================
// launch
// ============================================================================
extern "C" void kernel_launch(void* const* d_in, const int* in_sizes, int n_in,
                              void* d_out, int out_size) {
    const float* x   = (const float*)d_in[0];
    const float* pos = (const float*)d_in[1];
    const float* Wq  = (const float*)d_in[2];
    const float* Wk  = (const float*)d_in[3];
    const float* Wv  = (const float*)d_in[4];
    const float* P1  = (const float*)d_in[5];
    const float* pb1 = (const float*)d_in[6];
    const float* P2  = (const float*)d_in[7];
    const float* pb2 = (const float*)d_in[8];
    const float* A1  = (const float*)d_in[9];
    const float* ab1 = (const float*)d_in[10];
    const float* A2  = (const float*)d_in[11];
    const float* ab2 = (const float*)d_in[12];
    const float* Wf  = (const float*)d_in[13];
    const float* bf  = (const float*)d_in[14];
    float* out = (float*)d_out;

    cudaFuncSetAttribute(proj_kernel, cudaFuncAttributeMaxDynamicSharedMemorySize,
                         (int)sizeof(ProjSmem));
    cudaFuncSetAttribute(attn_kernel, cudaFuncAttributeMaxDynamicSharedMemorySize,
                         (int)sizeof(AttnSmem));

    knn_kernel<<<2048, 256>>>(pos);
    proj_kernel<<<1024, 1024, sizeof(ProjSmem)>>>(x, Wq, Wk, Wv);
    attn_kernel<<<NPOINTS_TOTAL, 1024, sizeof(AttnSmem)>>>(
        x, pos, P1, pb1, P2, pb2, A1, ab1, A2, ab2, Wf, bf, out);
}

// round 5
// speedup vs baseline: 1.3486x; 1.3486x over previous
#include <cuda_runtime.h>
#include <cuda_bf16.h>
#include <cstddef>
#include <cstdint>

#define BATCH 2
#define NPTS  8192
#define DIM   64
#define KNN   16
#define NPOINTS_TOTAL (BATCH * NPTS)
#define PPB   8   // points per attn block

// tf32 operand rounding for the K=64 GEMMs (cublas tf32 path emulation).
__device__ __forceinline__ float tf32r(float x) {
    uint32_t y;
    asm("cvt.rna.tf32.f32 %0, %1;" : "=r"(y) : "f"(x));
    return __uint_as_float(y);
}

// ---------------- scratch (static device globals; no runtime allocation) ----
__device__ float g_xq[NPOINTS_TOTAL * DIM];
__device__ float g_xk[NPOINTS_TOTAL * DIM];
__device__ float g_xv[NPOINTS_TOTAL * DIM];
__device__ int   g_idx[NPOINTS_TOTAL * KNN];

// ============================================================================
// KNN kernel (unchanged from passing R4): fp32 exact distances.
// ============================================================================
__global__ void __launch_bounds__(256) knn_kernel(const float* __restrict__ pos) {
    const int b    = blockIdx.x >> 10;
    const int blk  = blockIdx.x & 1023;
    const int wid  = threadIdx.x >> 5;
    const int lane = threadIdx.x & 31;
    const int n    = blk * 8 + wid;

    const float* posb = pos + (size_t)b * NPTS * 3;
    __shared__ float4 tile[1024];

    const float qx = posb[n * 3 + 0];
    const float qy = posb[n * 3 + 1];
    const float qz = posb[n * 3 + 2];
    const float sqq = __fadd_rn(__fadd_rn(__fmul_rn(qx, qx), __fmul_rn(qy, qy)),
                                __fmul_rn(qz, qz));

    float bd[16];
    int   bi[16];
#pragma unroll
    for (int i = 0; i < 16; i++) { bd[i] = 1e30f; bi[i] = 0x7fffffff; }
    float worst = 1e30f;
    int   worstid = 0x7fffffff;
    int   worstslot = 0;

    for (int base = 0; base < NPTS; base += 1024) {
        __syncthreads();
        for (int t = threadIdx.x; t < 1024; t += 256) {
            const int j = base + t;
            const float px = posb[j * 3 + 0];
            const float py = posb[j * 3 + 1];
            const float pz = posb[j * 3 + 2];
            const float sq = __fadd_rn(__fadd_rn(__fmul_rn(px, px), __fmul_rn(py, py)),
                                       __fmul_rn(pz, pz));
            tile[t] = make_float4(px, py, pz, sq);
        }
        __syncthreads();

        for (int t = lane; t < 1024; t += 32) {
            const float4 p = tile[t];
            const float dot = __fadd_rn(__fadd_rn(__fmul_rn(qx, p.x), __fmul_rn(qy, p.y)),
                                        __fmul_rn(qz, p.z));
            const float d2 = __fsub_rn(__fadd_rn(sqq, p.w), __fmul_rn(2.0f, dot));
            const int   j  = base + t;
            if (d2 < worst || (d2 == worst && j < worstid)) {
#pragma unroll
                for (int i = 0; i < 16; i++)
                    if (i == worstslot) { bd[i] = d2; bi[i] = j; }
                worst = bd[0]; worstid = bi[0]; worstslot = 0;
#pragma unroll
                for (int i = 1; i < 16; i++) {
                    const bool g = (bd[i] > worst) || (bd[i] == worst && bi[i] > worstid);
                    if (g) { worst = bd[i]; worstid = bi[i]; worstslot = i; }
                }
            }
        }
    }

#pragma unroll
    for (int sz = 2; sz <= 16; sz <<= 1) {
#pragma unroll
        for (int st = sz >> 1; st > 0; st >>= 1) {
#pragma unroll
            for (int i = 0; i < 16; i++) {
                const int j = i ^ st;
                if (j > i) {
                    const bool up = ((i & sz) == 0);
                    const bool gt = (bd[i] > bd[j]) || (bd[i] == bd[j] && bi[i] > bi[j]);
                    if (gt == up) {
                        const float td = bd[i]; bd[i] = bd[j]; bd[j] = td;
                        const int   ti = bi[i]; bi[i] = bi[j]; bi[j] = ti;
                    }
                }
            }
        }
    }

    const int outbase = ((b << 13) + n) * KNN;
#pragma unroll 1
    for (int r = 0; r < 16; r++) {
        float v  = bd[0];
        int   vid = bi[0];
#pragma unroll
        for (int off = 16; off > 0; off >>= 1) {
            const float ov  = __shfl_xor_sync(0xffffffffu, v, off);
            const int   oid = __shfl_xor_sync(0xffffffffu, vid, off);
            if (ov < v || (ov == v && oid < vid)) { v = ov; vid = oid; }
        }
        if (lane == 0) g_idx[outbase + r] = vid;
        if (vid == bi[0]) {
#pragma unroll
            for (int i = 0; i < 15; i++) { bd[i] = bd[i + 1]; bi[i] = bi[i + 1]; }
            bd[15] = 1e30f; bi[15] = 0x7fffffff;
        }
    }
}

// ============================================================================
// Projection kernel (unchanged from passing R4).
// ============================================================================
struct ProjSmem {
    float WqT[64 * 68];
    float WkT[64 * 68];
    float WvT[64 * 68];
    float xs[16 * 68];
};

__global__ void __launch_bounds__(1024) proj_kernel(const float* __restrict__ x,
                                                    const float* __restrict__ Wq,
                                                    const float* __restrict__ Wk,
                                                    const float* __restrict__ Wv) {
    extern __shared__ __align__(16) unsigned char proj_raw[];
    ProjSmem* S = reinterpret_cast<ProjSmem*>(proj_raw);

    const int tid = threadIdx.x;
    const int r = tid >> 6;
    const int d = tid & 63;

    for (int e = tid; e < 4096; e += 1024) {
        const int i = e >> 6, c = e & 63;
        S->WqT[c * 68 + i] = tf32r(Wq[e]);
        S->WkT[c * 68 + i] = tf32r(Wk[e]);
        S->WvT[c * 68 + i] = tf32r(Wv[e]);
    }
    const size_t rowbase = (size_t)blockIdx.x * 16;
    for (int e = tid; e < 16 * 64; e += 1024) {
        const int rr = e >> 6, c = e & 63;
        S->xs[rr * 68 + c] = tf32r(x[(rowbase + rr) * 64 + c]);
    }
    __syncthreads();

    const float4* xv4 = (const float4*)(S->xs + r * 68);
    const float4* wq4 = (const float4*)(S->WqT + d * 68);
    const float4* wk4 = (const float4*)(S->WkT + d * 68);
    const float4* wv4 = (const float4*)(S->WvT + d * 68);
    float aq = 0.f, ak = 0.f, av = 0.f;
#pragma unroll
    for (int i = 0; i < 16; i++) {
        const float4 xv = xv4[i];
        const float4 wq = wq4[i];
        const float4 wk = wk4[i];
        const float4 wv = wv4[i];
        aq = fmaf(wq.x, xv.x, aq); aq = fmaf(wq.y, xv.y, aq);
        aq = fmaf(wq.z, xv.z, aq); aq = fmaf(wq.w, xv.w, aq);
        ak = fmaf(wk.x, xv.x, ak); ak = fmaf(wk.y, xv.y, ak);
        ak = fmaf(wk.z, xv.z, ak); ak = fmaf(wk.w, xv.w, ak);
        av = fmaf(wv.x, xv.x, av); av = fmaf(wv.y, xv.y, av);
        av = fmaf(wv.z, xv.z, av); av = fmaf(wv.w, xv.w, av);
    }
    const size_t o = (rowbase + r) * 64 + d;
    g_xq[o] = aq; g_xk[o] = ak; g_xv[o] = av;
}

// ============================================================================
// Fused attention kernel v2: PPB=8 points per 1024-thread block.
// thread = (kk 0..15, d 0..63); loops over the 8 points with weight reuse.
// Numerics identical to the passing R4 kernel (same ops, same order).
// ============================================================================
struct AttnSmem {
    float P2T[64 * 68];
    float A1T[64 * 68];
    float A2T[64 * 68];
    float WfT[64 * 68];
    float P1s[3 * 64];
    float pb1s[64], pb2s[64], ab1s[64], ab2s[64], bfs[64];
    float qs[PPB * 64];
    float posn[PPB * 4];
    float rel[PPB * 16 * 4];
    float buf[PPB * 16 * 68];    // hid -> h -> t (pitch 68, float4 rows)
    float peb[PPB * 16 * 64];
    float abuf[PPB * 16 * 64];
    float ebuf[PPB * 16 * 64];
    float agg[PPB * 64];
};

__global__ void __launch_bounds__(1024, 1) attn_kernel(
    const float* __restrict__ x,
    const float* __restrict__ pos,
    const float* __restrict__ P1,
    const float* __restrict__ pb1,
    const float* __restrict__ P2,
    const float* __restrict__ pb2,
    const float* __restrict__ A1,
    const float* __restrict__ ab1,
    const float* __restrict__ A2,
    const float* __restrict__ ab2,
    const float* __restrict__ Wf,
    const float* __restrict__ bf,
    float* __restrict__ out) {
    extern __shared__ __align__(16) unsigned char attn_raw[];
    AttnSmem* S = reinterpret_cast<AttnSmem*>(attn_raw);

    const int tid   = threadIdx.x;
    const int kk    = tid >> 6;
    const int d     = tid & 63;
    const int pbase = blockIdx.x * PPB;

    // ---- stage weights (tf32), biases, q rows, center positions ----
    for (int e = tid; e < 4096; e += 1024) {
        const int i = e >> 6, c = e & 63;
        S->P2T[c * 68 + i] = tf32r(P2[e]);
        S->A1T[c * 68 + i] = tf32r(A1[e]);
        S->A2T[c * 68 + i] = tf32r(A2[e]);
        S->WfT[c * 68 + i] = tf32r(Wf[e]);
    }
    if (tid < 192) S->P1s[tid] = P1[tid];
    if (tid < 64) {
        S->pb1s[tid] = pb1[tid];
        S->pb2s[tid] = pb2[tid];
        S->ab1s[tid] = ab1[tid];
        S->ab2s[tid] = ab2[tid];
        S->bfs[tid]  = bf[tid];
    }
    if (tid < PPB * 64) S->qs[tid] = g_xq[(size_t)pbase * 64 + tid];
    if (tid < PPB * 3) {
        const int p = tid / 3, c = tid % 3;
        S->posn[p * 4 + c] = pos[(size_t)(pbase + p) * 3 + c];
    }

    // neighbor global rows for this thread's kk across the 8 points
    int grow[PPB];
#pragma unroll
    for (int p = 0; p < PPB; p++) {
        const int pnt = pbase + p;
        const int nb  = g_idx[pnt * KNN + kk];
        grow[p] = ((pnt >> 13) << 13) + nb;   // b*NPTS + nb
    }
    __syncthreads();

    // ---- rel = posn - knn_xyz ----
    for (int e = tid; e < PPB * 16 * 3; e += 1024) {
        const int p  = e / 48;
        const int r  = e % 48;
        const int kj = r / 3, c = r % 3;
        const int pnt = pbase + p;
        const int nb  = g_idx[pnt * KNN + kj];
        const int gr  = ((pnt >> 13) << 13) + nb;
        S->rel[(p * 16 + kj) * 4 + c] = S->posn[p * 4 + c] - pos[(size_t)gr * 3 + c];
    }
    __syncthreads();

    // ---- hidden = relu(rel @ P1 + pb1)  (fp32 elementwise lowering) ----
    {
        const float w0 = S->P1s[d], w1 = S->P1s[64 + d], w2 = S->P1s[128 + d];
        const float b1 = S->pb1s[d];
#pragma unroll
        for (int p = 0; p < PPB; p++) {
            const float r0 = S->rel[(p * 16 + kk) * 4 + 0];
            const float r1 = S->rel[(p * 16 + kk) * 4 + 1];
            const float r2 = S->rel[(p * 16 + kk) * 4 + 2];
            const float dotp = __fadd_rn(__fadd_rn(__fmul_rn(r0, w0), __fmul_rn(r1, w1)),
                                         __fmul_rn(r2, w2));
            const float hd = __fadd_rn(dotp, b1);
            S->buf[(p * 16 + kk) * 68 + d] = tf32r(fmaxf(hd, 0.f));
        }
    }
    __syncthreads();

    // ---- pe = hidden @ P2 + pb2  (tf32 operands, fp32 acc; weight reuse x8) ----
    {
        float acc[PPB];
#pragma unroll
        for (int p = 0; p < PPB; p++) acc[p] = S->pb2s[d];
        const float4* w4 = (const float4*)(S->P2T + d * 68);
        const float4* h4 = (const float4*)(S->buf);
#pragma unroll
        for (int i = 0; i < 16; i++) {
            const float4 w = w4[i];
#pragma unroll
            for (int p = 0; p < PPB; p++) {
                const float4 h = h4[(p * 16 + kk) * 17 + i];
                acc[p] = fmaf(w.x, h.x, acc[p]); acc[p] = fmaf(w.y, h.y, acc[p]);
                acc[p] = fmaf(w.z, h.z, acc[p]); acc[p] = fmaf(w.w, h.w, acc[p]);
            }
        }
#pragma unroll
        for (int p = 0; p < PPB; p++)
            S->peb[(p * 16 + kk) * 64 + d] = acc[p];
    }
    __syncthreads();   // all hid reads done

    // ---- h = q - k + pe  (stored tf32 as A1 operand) ----
#pragma unroll
    for (int p = 0; p < PPB; p++) {
        const float kval = g_xk[(size_t)grow[p] * 64 + d];
        const float pe   = S->peb[(p * 16 + kk) * 64 + d];
        S->buf[(p * 16 + kk) * 68 + d] = tf32r(S->qs[p * 64 + d] - kval + pe);
    }
    __syncthreads();

    // ---- t = relu(h @ A1 + ab1) ----
    {
        float acc[PPB];
#pragma unroll
        for (int p = 0; p < PPB; p++) acc[p] = S->ab1s[d];
        const float4* w4 = (const float4*)(S->A1T + d * 68);
        const float4* h4 = (const float4*)(S->buf);
#pragma unroll
        for (int i = 0; i < 16; i++) {
            const float4 w = w4[i];
#pragma unroll
            for (int p = 0; p < PPB; p++) {
                const float4 h = h4[(p * 16 + kk) * 17 + i];
                acc[p] = fmaf(w.x, h.x, acc[p]); acc[p] = fmaf(w.y, h.y, acc[p]);
                acc[p] = fmaf(w.z, h.z, acc[p]); acc[p] = fmaf(w.w, h.w, acc[p]);
            }
        }
        __syncthreads();   // all h reads done before overwrite
#pragma unroll
        for (int p = 0; p < PPB; p++)
            S->buf[(p * 16 + kk) * 68 + d] = tf32r(fmaxf(acc[p], 0.f));
    }
    __syncthreads();

    // ---- a = t @ A2 + ab2 -> abuf ----
    float aval[PPB];
    {
#pragma unroll
        for (int p = 0; p < PPB; p++) aval[p] = S->ab2s[d];
        const float4* w4 = (const float4*)(S->A2T + d * 68);
        const float4* h4 = (const float4*)(S->buf);
#pragma unroll
        for (int i = 0; i < 16; i++) {
            const float4 w = w4[i];
#pragma unroll
            for (int p = 0; p < PPB; p++) {
                const float4 h = h4[(p * 16 + kk) * 17 + i];
                aval[p] = fmaf(w.x, h.x, aval[p]); aval[p] = fmaf(w.y, h.y, aval[p]);
                aval[p] = fmaf(w.z, h.z, aval[p]); aval[p] = fmaf(w.w, h.w, aval[p]);
            }
        }
#pragma unroll
        for (int p = 0; p < PPB; p++)
            S->abuf[(p * 16 + kk) * 64 + d] = aval[p];
    }
    __syncthreads();

    // ---- softmax over neighbors (axis k) ----
    float ev[PPB];
#pragma unroll
    for (int p = 0; p < PPB; p++) {
        float m = -1e30f;
#pragma unroll
        for (int j = 0; j < 16; j++) m = fmaxf(m, S->abuf[(p * 16 + j) * 64 + d]);
        ev[p] = __expf((aval[p] - m) * 0.125f);
    }
    // write e (separate buffer, no conflict with abuf reads above)
#pragma unroll
    for (int p = 0; p < PPB; p++)
        S->ebuf[(p * 16 + kk) * 64 + d] = ev[p];
    __syncthreads();

    // contrib = (e/s) * (v + pe) -> abuf (abuf reads all complete)
#pragma unroll
    for (int p = 0; p < PPB; p++) {
        float s = 0.f;
#pragma unroll
        for (int j = 0; j < 16; j++) s += S->ebuf[(p * 16 + j) * 64 + d];
        const float attn = ev[p] / s;
        const float vval = g_xv[(size_t)grow[p] * 64 + d];
        const float pe   = S->peb[(p * 16 + kk) * 64 + d];
        S->abuf[(p * 16 + kk) * 64 + d] = attn * (vval + pe);
    }
    __syncthreads();

    // ---- agg = sum_k contrib (threads kk<8 handle p=kk) ----
    if (kk < PPB) {
        const int p = kk;
        float ag = 0.f;
#pragma unroll
        for (int j = 0; j < 16; j++) ag += S->abuf[(p * 16 + j) * 64 + d];
        S->agg[p * 64 + d] = tf32r(ag);
    }
    __syncthreads();

    // ---- out = agg @ Wf + bf + x ----
    if (kk < PPB) {
        const int p = kk;
        float o = S->bfs[d] + x[(size_t)(pbase + p) * 64 + d];
        const float4* w4 = (const float4*)(S->WfT + d * 68);
        const float4* g4 = (const float4*)(S->agg + p * 64);
#pragma unroll
        for (int i = 0; i < 16; i++) {
            const float4 w = w4[i];
            const float4 g = g4[i];
            o = fmaf(w.x, g.x, o); o = fmaf(w.y, g.y, o);
            o = fmaf(w.z, g.z, o); o = fmaf(w.w, g.w, o);
        }
        out[(size_t)(pbase + p) * 64 + d] = o;
    }
}

// ============================================================================
// launch
// ============================================================================
extern "C" void kernel_launch(void* const* d_in, const int* in_sizes, int n_in,
                              void* d_out, int out_size) {
    const float* x   = (const float*)d_in[0];
    const float* pos = (const float*)d_in[1];
    const float* Wq  = (const float*)d_in[2];
    const float* Wk  = (const float*)d_in[3];
    const float* Wv  = (const float*)d_in[4];
    const float* P1  = (const float*)d_in[5];
    const float* pb1 = (const float*)d_in[6];
    const float* P2  = (const float*)d_in[7];
    const float* pb2 = (const float*)d_in[8];
    const float* A1  = (const float*)d_in[9];
    const float* ab1 = (const float*)d_in[10];
    const float* A2  = (const float*)d_in[11];
    const float* ab2 = (const float*)d_in[12];
    const float* Wf  = (const float*)d_in[13];
    const float* bf  = (const float*)d_in[14];
    float* out = (float*)d_out;

    cudaFuncSetAttribute(proj_kernel, cudaFuncAttributeMaxDynamicSharedMemorySize,
                         (int)sizeof(ProjSmem));
    cudaFuncSetAttribute(attn_kernel, cudaFuncAttributeMaxDynamicSharedMemorySize,
                         (int)sizeof(AttnSmem));

    knn_kernel<<<2048, 256>>>(pos);
    proj_kernel<<<1024, 1024, sizeof(ProjSmem)>>>(x, Wq, Wk, Wv);
    attn_kernel<<<NPOINTS_TOTAL / PPB, 1024, sizeof(AttnSmem)>>>(
        x, pos, P1, pb1, P2, pb2, A1, ab1, A2, ab2, Wf, bf, out);
}

// round 6
// speedup vs baseline: 1.4969x; 1.1100x over previous
#include <cuda_runtime.h>
#include <cuda_bf16.h>
#include <cstddef>
#include <cstdint>

#define BATCH 2
#define NPTS  8192
#define DIM   64
#define KNN   16
#define NPOINTS_TOTAL (BATCH * NPTS)
#define PPB   8    // points per attn block (128 rows)

// tf32 operand rounding for the K=64 GEMMs (cublas tf32 path emulation).
__device__ __forceinline__ float tf32r(float x) {
    uint32_t y;
    asm("cvt.rna.tf32.f32 %0, %1;" : "=r"(y) : "f"(x));
    return __uint_as_float(y);
}

// ---------------- scratch (static device globals; no runtime allocation) ----
__device__ float g_xq[NPOINTS_TOTAL * DIM];
__device__ float g_xk[NPOINTS_TOTAL * DIM];
__device__ float g_xv[NPOINTS_TOTAL * DIM];
__device__ int   g_idx[NPOINTS_TOTAL * KNN];

// ============================================================================
// KNN kernel (unchanged from passing R4/R5): fp32 exact distances.
// ============================================================================
__global__ void __launch_bounds__(256) knn_kernel(const float* __restrict__ pos) {
    const int b    = blockIdx.x >> 10;
    const int blk  = blockIdx.x & 1023;
    const int wid  = threadIdx.x >> 5;
    const int lane = threadIdx.x & 31;
    const int n    = blk * 8 + wid;

    const float* posb = pos + (size_t)b * NPTS * 3;
    __shared__ float4 tile[1024];

    const float qx = posb[n * 3 + 0];
    const float qy = posb[n * 3 + 1];
    const float qz = posb[n * 3 + 2];
    const float sqq = __fadd_rn(__fadd_rn(__fmul_rn(qx, qx), __fmul_rn(qy, qy)),
                                __fmul_rn(qz, qz));

    float bd[16];
    int   bi[16];
#pragma unroll
    for (int i = 0; i < 16; i++) { bd[i] = 1e30f; bi[i] = 0x7fffffff; }
    float worst = 1e30f;
    int   worstid = 0x7fffffff;
    int   worstslot = 0;

    for (int base = 0; base < NPTS; base += 1024) {
        __syncthreads();
        for (int t = threadIdx.x; t < 1024; t += 256) {
            const int j = base + t;
            const float px = posb[j * 3 + 0];
            const float py = posb[j * 3 + 1];
            const float pz = posb[j * 3 + 2];
            const float sq = __fadd_rn(__fadd_rn(__fmul_rn(px, px), __fmul_rn(py, py)),
                                       __fmul_rn(pz, pz));
            tile[t] = make_float4(px, py, pz, sq);
        }
        __syncthreads();

        for (int t = lane; t < 1024; t += 32) {
            const float4 p = tile[t];
            const float dot = __fadd_rn(__fadd_rn(__fmul_rn(qx, p.x), __fmul_rn(qy, p.y)),
                                        __fmul_rn(qz, p.z));
            const float d2 = __fsub_rn(__fadd_rn(sqq, p.w), __fmul_rn(2.0f, dot));
            const int   j  = base + t;
            if (d2 < worst || (d2 == worst && j < worstid)) {
#pragma unroll
                for (int i = 0; i < 16; i++)
                    if (i == worstslot) { bd[i] = d2; bi[i] = j; }
                worst = bd[0]; worstid = bi[0]; worstslot = 0;
#pragma unroll
                for (int i = 1; i < 16; i++) {
                    const bool g = (bd[i] > worst) || (bd[i] == worst && bi[i] > worstid);
                    if (g) { worst = bd[i]; worstid = bi[i]; worstslot = i; }
                }
            }
        }
    }

#pragma unroll
    for (int sz = 2; sz <= 16; sz <<= 1) {
#pragma unroll
        for (int st = sz >> 1; st > 0; st >>= 1) {
#pragma unroll
            for (int i = 0; i < 16; i++) {
                const int j = i ^ st;
                if (j > i) {
                    const bool up = ((i & sz) == 0);
                    const bool gt = (bd[i] > bd[j]) || (bd[i] == bd[j] && bi[i] > bi[j]);
                    if (gt == up) {
                        const float td = bd[i]; bd[i] = bd[j]; bd[j] = td;
                        const int   ti = bi[i]; bi[i] = bi[j]; bi[j] = ti;
                    }
                }
            }
        }
    }

    const int outbase = ((b << 13) + n) * KNN;
#pragma unroll 1
    for (int r = 0; r < 16; r++) {
        float v  = bd[0];
        int   vid = bi[0];
#pragma unroll
        for (int off = 16; off > 0; off >>= 1) {
            const float ov  = __shfl_xor_sync(0xffffffffu, v, off);
            const int   oid = __shfl_xor_sync(0xffffffffu, vid, off);
            if (ov < v || (ov == v && oid < vid)) { v = ov; vid = oid; }
        }
        if (lane == 0) g_idx[outbase + r] = vid;
        if (vid == bi[0]) {
#pragma unroll
            for (int i = 0; i < 15; i++) { bd[i] = bd[i + 1]; bi[i] = bi[i + 1]; }
            bd[15] = 1e30f; bi[15] = 0x7fffffff;
        }
    }
}

// ============================================================================
// Projection kernel (unchanged from passing R4/R5).
// ============================================================================
struct ProjSmem {
    float WqT[64 * 68];
    float WkT[64 * 68];
    float WvT[64 * 68];
    float xs[16 * 68];
};

__global__ void __launch_bounds__(1024) proj_kernel(const float* __restrict__ x,
                                                    const float* __restrict__ Wq,
                                                    const float* __restrict__ Wk,
                                                    const float* __restrict__ Wv) {
    extern __shared__ __align__(16) unsigned char proj_raw[];
    ProjSmem* S = reinterpret_cast<ProjSmem*>(proj_raw);

    const int tid = threadIdx.x;
    const int r = tid >> 6;
    const int d = tid & 63;

    for (int e = tid; e < 4096; e += 1024) {
        const int i = e >> 6, c = e & 63;
        S->WqT[c * 68 + i] = tf32r(Wq[e]);
        S->WkT[c * 68 + i] = tf32r(Wk[e]);
        S->WvT[c * 68 + i] = tf32r(Wv[e]);
    }
    const size_t rowbase = (size_t)blockIdx.x * 16;
    for (int e = tid; e < 16 * 64; e += 1024) {
        const int rr = e >> 6, c = e & 63;
        S->xs[rr * 68 + c] = tf32r(x[(rowbase + rr) * 64 + c]);
    }
    __syncthreads();

    const float4* xv4 = (const float4*)(S->xs + r * 68);
    const float4* wq4 = (const float4*)(S->WqT + d * 68);
    const float4* wk4 = (const float4*)(S->WkT + d * 68);
    const float4* wv4 = (const float4*)(S->WvT + d * 68);
    float aq = 0.f, ak = 0.f, av = 0.f;
#pragma unroll
    for (int i = 0; i < 16; i++) {
        const float4 xv = xv4[i];
        const float4 wq = wq4[i];
        const float4 wk = wk4[i];
        const float4 wv = wv4[i];
        aq = fmaf(wq.x, xv.x, aq); aq = fmaf(wq.y, xv.y, aq);
        aq = fmaf(wq.z, xv.z, aq); aq = fmaf(wq.w, xv.w, aq);
        ak = fmaf(wk.x, xv.x, ak); ak = fmaf(wk.y, xv.y, ak);
        ak = fmaf(wk.z, xv.z, ak); ak = fmaf(wk.w, xv.w, ak);
        av = fmaf(wv.x, xv.x, av); av = fmaf(wv.y, xv.y, av);
        av = fmaf(wv.z, xv.z, av); av = fmaf(wv.w, xv.w, av);
    }
    const size_t o = (rowbase + r) * 64 + d;
    g_xq[o] = aq; g_xk[o] = ak; g_xv[o] = av;
}

// ============================================================================
// Attention kernel v3: register-blocked GEMM. 256 threads, 8 points/block.
// Rows m = p*16+kk (128). Thread (tx 0..15, ty 0..15) owns rows ty*8..+7,
// cols tx*4..+3. pe / a / softmax in registers; softmax partner = tid^16.
// Weight matrices staged one-at-a-time into a single 17 KB buffer.
// ============================================================================
struct AttnSmem {
    float actA[128 * 68];
    float actB[128 * 68];
    float wbuf[64 * 68];      // current weight matrix [k][n], tf32
    float qs[PPB * 68];
    float agg[PPB * 68];
    float rel[128 * 4];
    float P1s[3 * 64];
    float pb1s[64], pb2s[64], ab1s[64], ab2s[64], bfs[64];
};

__device__ __forceinline__ void stage_w(float* __restrict__ dst,
                                        const float* __restrict__ W, int tid) {
    for (int e = tid; e < 4096; e += 256)
        dst[(e >> 6) * 68 + (e & 63)] = tf32r(W[e]);
}

__global__ void __launch_bounds__(256, 2) attn_kernel(
    const float* __restrict__ x,
    const float* __restrict__ pos,
    const float* __restrict__ P1,
    const float* __restrict__ pb1,
    const float* __restrict__ P2,
    const float* __restrict__ pb2,
    const float* __restrict__ A1,
    const float* __restrict__ ab1,
    const float* __restrict__ A2,
    const float* __restrict__ ab2,
    const float* __restrict__ Wf,
    const float* __restrict__ bf,
    float* __restrict__ out) {
    extern __shared__ __align__(16) unsigned char attn_raw[];
    AttnSmem* S = reinterpret_cast<AttnSmem*>(attn_raw);

    const int tid = threadIdx.x;
    const int tx  = tid & 15;          // col tile
    const int ty  = tid >> 4;          // row tile
    const int n0  = tx * 4;
    const int m0  = ty * 8;
    const int p   = ty >> 1;           // point of this thread's rows
    const int pbase = blockIdx.x * PPB;
    const int b   = pbase >> 13;       // all 8 points in same batch

    // ---- stage0: biases, P1, q, rel, W_P2 ----
    if (tid < 192) S->P1s[tid] = P1[tid];
    if (tid < 64) {
        S->pb1s[tid] = pb1[tid];
        S->pb2s[tid] = pb2[tid];
        S->ab1s[tid] = ab1[tid];
        S->ab2s[tid] = ab2[tid];
        S->bfs[tid]  = bf[tid];
    }
    for (int e = tid; e < PPB * 64; e += 256)
        S->qs[(e >> 6) * 68 + (e & 63)] = g_xq[(size_t)pbase * 64 + e];

    // neighbor rows for this thread's 8 rows (broadcast loads within warp)
    int grow[8];
#pragma unroll
    for (int r = 0; r < 8; r++)
        grow[r] = (b << 13) + g_idx[pbase * KNN + m0 + r];

    for (int e = tid; e < 128 * 3; e += 256) {
        const int m = e / 3, c = e % 3;
        const int pp = m >> 4;
        const int nb = g_idx[pbase * KNN + m];
        S->rel[m * 4 + c] = pos[(size_t)(pbase + pp) * 3 + c]
                          - pos[((size_t)(b << 13) + nb) * 3 + c];
    }
    stage_w(S->wbuf, P2, tid);
    __syncthreads();

    // ---- hidden = relu(rel @ P1 + pb1) (fp32 elementwise order) -> actA ----
    {
        float4* a4 = (float4*)(S->actA);
#pragma unroll
        for (int r = 0; r < 8; r++) {
            const int m = m0 + r;
            const float r0 = S->rel[m * 4 + 0];
            const float r1 = S->rel[m * 4 + 1];
            const float r2 = S->rel[m * 4 + 2];
            float4 hv;
#pragma unroll
            for (int c = 0; c < 4; c++) {
                const int n = n0 + c;
                const float dotp = __fadd_rn(__fadd_rn(__fmul_rn(r0, S->P1s[n]),
                                                       __fmul_rn(r1, S->P1s[64 + n])),
                                             __fmul_rn(r2, S->P1s[128 + n]));
                const float hd = __fadd_rn(dotp, S->pb1s[n]);
                ((float*)&hv)[c] = tf32r(fmaxf(hd, 0.f));
            }
            a4[m * 17 + tx] = hv;
        }
    }
    __syncthreads();

    // =========== GEMM helper (as a lambda-free macro pattern) ===========
    float acc[8][4];
    float pe[8][4];
    const float4* wb4 = (const float4*)(S->wbuf);

#define GEMM_PHASE(INBUF)                                                     \
    {                                                                         \
        const float4* in4 = (const float4*)(INBUF);                           \
        _Pragma("unroll 2")                                                   \
        for (int kq = 0; kq < 16; kq++) {                                     \
            const float4 w0 = wb4[(4 * kq + 0) * 17 + tx];                    \
            const float4 w1 = wb4[(4 * kq + 1) * 17 + tx];                    \
            const float4 w2 = wb4[(4 * kq + 2) * 17 + tx];                    \
            const float4 w3 = wb4[(4 * kq + 3) * 17 + tx];                    \
            _Pragma("unroll")                                                 \
            for (int r = 0; r < 8; r++) {                                     \
                const float4 a = in4[(m0 + r) * 17 + kq];                     \
                acc[r][0] = fmaf(a.x, w0.x, acc[r][0]);                       \
                acc[r][0] = fmaf(a.y, w1.x, acc[r][0]);                       \
                acc[r][0] = fmaf(a.z, w2.x, acc[r][0]);                       \
                acc[r][0] = fmaf(a.w, w3.x, acc[r][0]);                       \
                acc[r][1] = fmaf(a.x, w0.y, acc[r][1]);                       \
                acc[r][1] = fmaf(a.y, w1.y, acc[r][1]);                       \
                acc[r][1] = fmaf(a.z, w2.y, acc[r][1]);                       \
                acc[r][1] = fmaf(a.w, w3.y, acc[r][1]);                       \
                acc[r][2] = fmaf(a.x, w0.z, acc[r][2]);                       \
                acc[r][2] = fmaf(a.y, w1.z, acc[r][2]);                       \
                acc[r][2] = fmaf(a.z, w2.z, acc[r][2]);                       \
                acc[r][2] = fmaf(a.w, w3.z, acc[r][2]);                       \
                acc[r][3] = fmaf(a.x, w0.w, acc[r][3]);                       \
                acc[r][3] = fmaf(a.y, w1.w, acc[r][3]);                       \
                acc[r][3] = fmaf(a.z, w2.w, acc[r][3]);                       \
                acc[r][3] = fmaf(a.w, w3.w, acc[r][3]);                       \
            }                                                                 \
        }                                                                     \
    }

    // ---- GEMM1: pe = hidden @ P2 + pb2 ; h = q - k + pe -> actB (tf32) ----
#pragma unroll
    for (int r = 0; r < 8; r++)
#pragma unroll
        for (int c = 0; c < 4; c++) acc[r][c] = S->pb2s[n0 + c];
    GEMM_PHASE(S->actA);
    {
        const float4 qv = ((const float4*)(S->qs))[p * 17 + tx];
        float4* b4 = (float4*)(S->actB);
#pragma unroll
        for (int r = 0; r < 8; r++) {
            const float4 kv = *(const float4*)(g_xk + (size_t)grow[r] * 64 + n0);
#pragma unroll
            for (int c = 0; c < 4; c++) pe[r][c] = acc[r][c];
            float4 hv;
            hv.x = tf32r(qv.x - kv.x + pe[r][0]);
            hv.y = tf32r(qv.y - kv.y + pe[r][1]);
            hv.z = tf32r(qv.z - kv.z + pe[r][2]);
            hv.w = tf32r(qv.w - kv.w + pe[r][3]);
            b4[(m0 + r) * 17 + tx] = hv;
        }
    }
    __syncthreads();
    stage_w(S->wbuf, A1, tid);
    __syncthreads();

    // ---- GEMM2: t = relu(h @ A1 + ab1) -> actA (tf32) ----
#pragma unroll
    for (int r = 0; r < 8; r++)
#pragma unroll
        for (int c = 0; c < 4; c++) acc[r][c] = S->ab1s[n0 + c];
    GEMM_PHASE(S->actB);
    {
        float4* a4 = (float4*)(S->actA);
#pragma unroll
        for (int r = 0; r < 8; r++) {
            float4 tv;
            tv.x = tf32r(fmaxf(acc[r][0], 0.f));
            tv.y = tf32r(fmaxf(acc[r][1], 0.f));
            tv.z = tf32r(fmaxf(acc[r][2], 0.f));
            tv.w = tf32r(fmaxf(acc[r][3], 0.f));
            a4[(m0 + r) * 17 + tx] = tv;
        }
    }
    __syncthreads();
    stage_w(S->wbuf, A2, tid);
    __syncthreads();

    // ---- GEMM3: a = t @ A2 + ab2 (regs) ; softmax ; agg ----
#pragma unroll
    for (int r = 0; r < 8; r++)
#pragma unroll
        for (int c = 0; c < 4; c++) acc[r][c] = S->ab2s[n0 + c];
    GEMM_PHASE(S->actA);
    {
        // softmax over the 16 rows of this point; partner thread = tid^16
        float ev[8][4];
#pragma unroll
        for (int c = 0; c < 4; c++) {
            float m = acc[0][c];
#pragma unroll
            for (int r = 1; r < 8; r++) m = fmaxf(m, acc[r][c]);
            const float om = __shfl_xor_sync(0xffffffffu, m, 16);
            m = fmaxf(m, om);
            float s = 0.f;
#pragma unroll
            for (int r = 0; r < 8; r++) {
                ev[r][c] = __expf((acc[r][c] - m) * 0.125f);
                s += ev[r][c];
            }
            s += __shfl_xor_sync(0xffffffffu, s, 16);
#pragma unroll
            for (int r = 0; r < 8; r++) ev[r][c] /= s;
        }
        // agg = sum_k attn * (v + pe)
        float ag[4] = {0.f, 0.f, 0.f, 0.f};
#pragma unroll
        for (int r = 0; r < 8; r++) {
            const float4 vv = *(const float4*)(g_xv + (size_t)grow[r] * 64 + n0);
            ag[0] += ev[r][0] * (vv.x + pe[r][0]);
            ag[1] += ev[r][1] * (vv.y + pe[r][1]);
            ag[2] += ev[r][2] * (vv.z + pe[r][2]);
            ag[3] += ev[r][3] * (vv.w + pe[r][3]);
        }
#pragma unroll
        for (int c = 0; c < 4; c++)
            ag[c] += __shfl_xor_sync(0xffffffffu, ag[c], 16);
        if ((ty & 1) == 0) {
            float4 av;
            av.x = tf32r(ag[0]); av.y = tf32r(ag[1]);
            av.z = tf32r(ag[2]); av.w = tf32r(ag[3]);
            ((float4*)(S->agg))[p * 17 + tx] = av;
        }
    }
    __syncthreads();
    stage_w(S->wbuf, Wf, tid);
    __syncthreads();

    // ---- out = agg @ Wf + bf + x  (512 outputs, 2 per thread) ----
#pragma unroll
    for (int t2 = 0; t2 < 2; t2++) {
        const int oi = tid + 256 * t2;
        const int pp = oi >> 6;
        const int n  = oi & 63;
        float o = S->bfs[n] + x[(size_t)(pbase + pp) * 64 + n];
        const float* ar = S->agg + pp * 68;
#pragma unroll
        for (int k = 0; k < 64; k++)
            o = fmaf(ar[k], S->wbuf[k * 68 + n], o);
        out[(size_t)(pbase + pp) * 64 + n] = o;
    }
#undef GEMM_PHASE
}

// ============================================================================
// launch
// ============================================================================
extern "C" void kernel_launch(void* const* d_in, const int* in_sizes, int n_in,
                              void* d_out, int out_size) {
    const float* x   = (const float*)d_in[0];
    const float* pos = (const float*)d_in[1];
    const float* Wq  = (const float*)d_in[2];
    const float* Wk  = (const float*)d_in[3];
    const float* Wv  = (const float*)d_in[4];
    const float* P1  = (const float*)d_in[5];
    const float* pb1 = (const float*)d_in[6];
    const float* P2  = (const float*)d_in[7];
    const float* pb2 = (const float*)d_in[8];
    const float* A1  = (const float*)d_in[9];
    const float* ab1 = (const float*)d_in[10];
    const float* A2  = (const float*)d_in[11];
    const float* ab2 = (const float*)d_in[12];
    const float* Wf  = (const float*)d_in[13];
    const float* bf  = (const float*)d_in[14];
    float* out = (float*)d_out;

    cudaFuncSetAttribute(proj_kernel, cudaFuncAttributeMaxDynamicSharedMemorySize,
                         (int)sizeof(ProjSmem));
    cudaFuncSetAttribute(attn_kernel, cudaFuncAttributeMaxDynamicSharedMemorySize,
                         (int)sizeof(AttnSmem));

    knn_kernel<<<2048, 256>>>(pos);
    proj_kernel<<<1024, 1024, sizeof(ProjSmem)>>>(x, Wq, Wk, Wv);
    attn_kernel<<<NPOINTS_TOTAL / PPB, 256, sizeof(AttnSmem)>>>(
        x, pos, P1, pb1, P2, pb2, A1, ab1, A2, ab2, Wf, bf, out);
}

// round 7
// speedup vs baseline: 4.6274x; 3.0913x over previous
#include <cuda_runtime.h>
#include <cuda_bf16.h>
#include <cstddef>
#include <cstdint>

#define BATCH 2
#define NPTS  8192
#define DIM   64
#define KNN   16
#define NPOINTS_TOTAL (BATCH * NPTS)
#define PPB   8    // points per attn block (128 rows)

// tf32 operand rounding for the K=64 GEMMs (cublas tf32 path emulation).
__device__ __forceinline__ float tf32r(float x) {
    uint32_t y;
    asm("cvt.rna.tf32.f32 %0, %1;" : "=r"(y) : "f"(x));
    return __uint_as_float(y);
}

// ---------------- scratch (static device globals; no runtime allocation) ----
__device__ float g_xq[NPOINTS_TOTAL * DIM];
__device__ float g_xk[NPOINTS_TOTAL * DIM];
__device__ float g_xv[NPOINTS_TOTAL * DIM];
__device__ int   g_idx[NPOINTS_TOTAL * KNN];

// ============================================================================
// KNN kernel v2: warp-collective top-16. Lanes 0..15 hold the sorted top list
// by (d2, idx) lexicographic (== jax top_k tie semantics). Common path is one
// ballot per 32 candidates; inserts are rare (~100/query) and warp-uniform.
// Distance arithmetic identical to the passing R4/R6 kernels.
// ============================================================================
__global__ void __launch_bounds__(256) knn_kernel(const float* __restrict__ pos) {
    const int b    = blockIdx.x >> 10;
    const int blk  = blockIdx.x & 1023;
    const int wid  = threadIdx.x >> 5;
    const int lane = threadIdx.x & 31;
    const int n    = blk * 8 + wid;
    const unsigned FULL = 0xffffffffu;

    const float* posb = pos + (size_t)b * NPTS * 3;
    __shared__ float4 tile[1024];

    const float qx = posb[n * 3 + 0];
    const float qy = posb[n * 3 + 1];
    const float qz = posb[n * 3 + 2];
    const float sqq = __fadd_rn(__fadd_rn(__fmul_rn(qx, qx), __fmul_rn(qy, qy)),
                                __fmul_rn(qz, qz));

    // distributed sorted top-16 (lanes 0..15); threshold = entry 15
    float kd = 1e30f;
    int   ki = 0x7fffffff;
    float thr   = 1e30f;
    int   thrid = 0x7fffffff;

    for (int base = 0; base < NPTS; base += 1024) {
        __syncthreads();
        for (int t = threadIdx.x; t < 1024; t += 256) {
            const int j = base + t;
            const float px = posb[j * 3 + 0];
            const float py = posb[j * 3 + 1];
            const float pz = posb[j * 3 + 2];
            const float sq = __fadd_rn(__fadd_rn(__fmul_rn(px, px), __fmul_rn(py, py)),
                                       __fmul_rn(pz, pz));
            tile[t] = make_float4(px, py, pz, sq);
        }
        __syncthreads();

#pragma unroll 4
        for (int it = 0; it < 32; it++) {
            const int t = it * 32 + lane;
            const float4 p = tile[t];
            const float dot = __fadd_rn(__fadd_rn(__fmul_rn(qx, p.x), __fmul_rn(qy, p.y)),
                                        __fmul_rn(qz, p.z));
            const float d2 = __fsub_rn(__fadd_rn(sqq, p.w), __fmul_rn(2.0f, dot));
            const int   j  = base + t;

            const bool qual = (d2 < thr) || (d2 == thr && j < thrid);
            unsigned mask = __ballot_sync(FULL, qual);
            while (mask) {
                const int src = __ffs(mask) - 1;
                mask &= mask - 1;
                const float nd = __shfl_sync(FULL, d2, src);
                const int   nj = __shfl_sync(FULL, j, src);
                // re-check: list may have tightened since the ballot
                if (nd < thr || (nd == thr && nj < thrid)) {
                    const bool less = (kd < nd) || (kd == nd && ki < nj);
                    const unsigned lm = __ballot_sync(FULL, less && (lane < 16));
                    const int pos = __popc(lm);
                    const float upkd = __shfl_up_sync(FULL, kd, 1);
                    const int   upki = __shfl_up_sync(FULL, ki, 1);
                    if (lane >= pos) {
                        if (lane == pos) { kd = nd; ki = nj; }
                        else             { kd = upkd; ki = upki; }
                    }
                    thr   = __shfl_sync(FULL, kd, 15);
                    thrid = __shfl_sync(FULL, ki, 15);
                }
            }
        }
    }

    if (lane < 16) g_idx[((b << 13) + n) * KNN + lane] = ki;
}

// ============================================================================
// Projection kernel (unchanged from passing R4/R5/R6).
// ============================================================================
struct ProjSmem {
    float WqT[64 * 68];
    float WkT[64 * 68];
    float WvT[64 * 68];
    float xs[16 * 68];
};

__global__ void __launch_bounds__(1024) proj_kernel(const float* __restrict__ x,
                                                    const float* __restrict__ Wq,
                                                    const float* __restrict__ Wk,
                                                    const float* __restrict__ Wv) {
    extern __shared__ __align__(16) unsigned char proj_raw[];
    ProjSmem* S = reinterpret_cast<ProjSmem*>(proj_raw);

    const int tid = threadIdx.x;
    const int r = tid >> 6;
    const int d = tid & 63;

    for (int e = tid; e < 4096; e += 1024) {
        const int i = e >> 6, c = e & 63;
        S->WqT[c * 68 + i] = tf32r(Wq[e]);
        S->WkT[c * 68 + i] = tf32r(Wk[e]);
        S->WvT[c * 68 + i] = tf32r(Wv[e]);
    }
    const size_t rowbase = (size_t)blockIdx.x * 16;
    for (int e = tid; e < 16 * 64; e += 1024) {
        const int rr = e >> 6, c = e & 63;
        S->xs[rr * 68 + c] = tf32r(x[(rowbase + rr) * 64 + c]);
    }
    __syncthreads();

    const float4* xv4 = (const float4*)(S->xs + r * 68);
    const float4* wq4 = (const float4*)(S->WqT + d * 68);
    const float4* wk4 = (const float4*)(S->WkT + d * 68);
    const float4* wv4 = (const float4*)(S->WvT + d * 68);
    float aq = 0.f, ak = 0.f, av = 0.f;
#pragma unroll
    for (int i = 0; i < 16; i++) {
        const float4 xv = xv4[i];
        const float4 wq = wq4[i];
        const float4 wk = wk4[i];
        const float4 wv = wv4[i];
        aq = fmaf(wq.x, xv.x, aq); aq = fmaf(wq.y, xv.y, aq);
        aq = fmaf(wq.z, xv.z, aq); aq = fmaf(wq.w, xv.w, aq);
        ak = fmaf(wk.x, xv.x, ak); ak = fmaf(wk.y, xv.y, ak);
        ak = fmaf(wk.z, xv.z, ak); ak = fmaf(wk.w, xv.w, ak);
        av = fmaf(wv.x, xv.x, av); av = fmaf(wv.y, xv.y, av);
        av = fmaf(wv.z, xv.z, av); av = fmaf(wv.w, xv.w, av);
    }
    const size_t o = (rowbase + r) * 64 + d;
    g_xq[o] = aq; g_xk[o] = ak; g_xv[o] = av;
}

// ============================================================================
// Attention kernel v3 (unchanged from passing R6): register-blocked GEMM.
// ============================================================================
struct AttnSmem {
    float actA[128 * 68];
    float actB[128 * 68];
    float wbuf[64 * 68];
    float qs[PPB * 68];
    float agg[PPB * 68];
    float rel[128 * 4];
    float P1s[3 * 64];
    float pb1s[64], pb2s[64], ab1s[64], ab2s[64], bfs[64];
};

__device__ __forceinline__ void stage_w(float* __restrict__ dst,
                                        const float* __restrict__ W, int tid) {
    for (int e = tid; e < 4096; e += 256)
        dst[(e >> 6) * 68 + (e & 63)] = tf32r(W[e]);
}

__global__ void __launch_bounds__(256, 2) attn_kernel(
    const float* __restrict__ x,
    const float* __restrict__ pos,
    const float* __restrict__ P1,
    const float* __restrict__ pb1,
    const float* __restrict__ P2,
    const float* __restrict__ pb2,
    const float* __restrict__ A1,
    const float* __restrict__ ab1,
    const float* __restrict__ A2,
    const float* __restrict__ ab2,
    const float* __restrict__ Wf,
    const float* __restrict__ bf,
    float* __restrict__ out) {
    extern __shared__ __align__(16) unsigned char attn_raw[];
    AttnSmem* S = reinterpret_cast<AttnSmem*>(attn_raw);

    const int tid = threadIdx.x;
    const int tx  = tid & 15;
    const int ty  = tid >> 4;
    const int n0  = tx * 4;
    const int m0  = ty * 8;
    const int p   = ty >> 1;
    const int pbase = blockIdx.x * PPB;
    const int b   = pbase >> 13;

    if (tid < 192) S->P1s[tid] = P1[tid];
    if (tid < 64) {
        S->pb1s[tid] = pb1[tid];
        S->pb2s[tid] = pb2[tid];
        S->ab1s[tid] = ab1[tid];
        S->ab2s[tid] = ab2[tid];
        S->bfs[tid]  = bf[tid];
    }
    for (int e = tid; e < PPB * 64; e += 256)
        S->qs[(e >> 6) * 68 + (e & 63)] = g_xq[(size_t)pbase * 64 + e];

    int grow[8];
#pragma unroll
    for (int r = 0; r < 8; r++)
        grow[r] = (b << 13) + g_idx[pbase * KNN + m0 + r];

    for (int e = tid; e < 128 * 3; e += 256) {
        const int m = e / 3, c = e % 3;
        const int pp = m >> 4;
        const int nb = g_idx[pbase * KNN + m];
        S->rel[m * 4 + c] = pos[(size_t)(pbase + pp) * 3 + c]
                          - pos[((size_t)(b << 13) + nb) * 3 + c];
    }
    stage_w(S->wbuf, P2, tid);
    __syncthreads();

    {
        float4* a4 = (float4*)(S->actA);
#pragma unroll
        for (int r = 0; r < 8; r++) {
            const int m = m0 + r;
            const float r0 = S->rel[m * 4 + 0];
            const float r1 = S->rel[m * 4 + 1];
            const float r2 = S->rel[m * 4 + 2];
            float4 hv;
#pragma unroll
            for (int c = 0; c < 4; c++) {
                const int n = n0 + c;
                const float dotp = __fadd_rn(__fadd_rn(__fmul_rn(r0, S->P1s[n]),
                                                       __fmul_rn(r1, S->P1s[64 + n])),
                                             __fmul_rn(r2, S->P1s[128 + n]));
                const float hd = __fadd_rn(dotp, S->pb1s[n]);
                ((float*)&hv)[c] = tf32r(fmaxf(hd, 0.f));
            }
            a4[m * 17 + tx] = hv;
        }
    }
    __syncthreads();

    float acc[8][4];
    float pe[8][4];
    const float4* wb4 = (const float4*)(S->wbuf);

#define GEMM_PHASE(INBUF)                                                     \
    {                                                                         \
        const float4* in4 = (const float4*)(INBUF);                           \
        _Pragma("unroll 2")                                                   \
        for (int kq = 0; kq < 16; kq++) {                                     \
            const float4 w0 = wb4[(4 * kq + 0) * 17 + tx];                    \
            const float4 w1 = wb4[(4 * kq + 1) * 17 + tx];                    \
            const float4 w2 = wb4[(4 * kq + 2) * 17 + tx];                    \
            const float4 w3 = wb4[(4 * kq + 3) * 17 + tx];                    \
            _Pragma("unroll")                                                 \
            for (int r = 0; r < 8; r++) {                                     \
                const float4 a = in4[(m0 + r) * 17 + kq];                     \
                acc[r][0] = fmaf(a.x, w0.x, acc[r][0]);                       \
                acc[r][0] = fmaf(a.y, w1.x, acc[r][0]);                       \
                acc[r][0] = fmaf(a.z, w2.x, acc[r][0]);                       \
                acc[r][0] = fmaf(a.w, w3.x, acc[r][0]);                       \
                acc[r][1] = fmaf(a.x, w0.y, acc[r][1]);                       \
                acc[r][1] = fmaf(a.y, w1.y, acc[r][1]);                       \
                acc[r][1] = fmaf(a.z, w2.y, acc[r][1]);                       \
                acc[r][1] = fmaf(a.w, w3.y, acc[r][1]);                       \
                acc[r][2] = fmaf(a.x, w0.z, acc[r][2]);                       \
                acc[r][2] = fmaf(a.y, w1.z, acc[r][2]);                       \
                acc[r][2] = fmaf(a.z, w2.z, acc[r][2]);                       \
                acc[r][2] = fmaf(a.w, w3.z, acc[r][2]);                       \
                acc[r][3] = fmaf(a.x, w0.w, acc[r][3]);                       \
                acc[r][3] = fmaf(a.y, w1.w, acc[r][3]);                       \
                acc[r][3] = fmaf(a.z, w2.w, acc[r][3]);                       \
                acc[r][3] = fmaf(a.w, w3.w, acc[r][3]);                       \
            }                                                                 \
        }                                                                     \
    }

#pragma unroll
    for (int r = 0; r < 8; r++)
#pragma unroll
        for (int c = 0; c < 4; c++) acc[r][c] = S->pb2s[n0 + c];
    GEMM_PHASE(S->actA);
    {
        const float4 qv = ((const float4*)(S->qs))[p * 17 + tx];
        float4* b4 = (float4*)(S->actB);
#pragma unroll
        for (int r = 0; r < 8; r++) {
            const float4 kv = *(const float4*)(g_xk + (size_t)grow[r] * 64 + n0);
#pragma unroll
            for (int c = 0; c < 4; c++) pe[r][c] = acc[r][c];
            float4 hv;
            hv.x = tf32r(qv.x - kv.x + pe[r][0]);
            hv.y = tf32r(qv.y - kv.y + pe[r][1]);
            hv.z = tf32r(qv.z - kv.z + pe[r][2]);
            hv.w = tf32r(qv.w - kv.w + pe[r][3]);
            b4[(m0 + r) * 17 + tx] = hv;
        }
    }
    __syncthreads();
    stage_w(S->wbuf, A1, tid);
    __syncthreads();

#pragma unroll
    for (int r = 0; r < 8; r++)
#pragma unroll
        for (int c = 0; c < 4; c++) acc[r][c] = S->ab1s[n0 + c];
    GEMM_PHASE(S->actB);
    {
        float4* a4 = (float4*)(S->actA);
#pragma unroll
        for (int r = 0; r < 8; r++) {
            float4 tv;
            tv.x = tf32r(fmaxf(acc[r][0], 0.f));
            tv.y = tf32r(fmaxf(acc[r][1], 0.f));
            tv.z = tf32r(fmaxf(acc[r][2], 0.f));
            tv.w = tf32r(fmaxf(acc[r][3], 0.f));
            a4[(m0 + r) * 17 + tx] = tv;
        }
    }
    __syncthreads();
    stage_w(S->wbuf, A2, tid);
    __syncthreads();

#pragma unroll
    for (int r = 0; r < 8; r++)
#pragma unroll
        for (int c = 0; c < 4; c++) acc[r][c] = S->ab2s[n0 + c];
    GEMM_PHASE(S->actA);
    {
        float ev[8][4];
#pragma unroll
        for (int c = 0; c < 4; c++) {
            float m = acc[0][c];
#pragma unroll
            for (int r = 1; r < 8; r++) m = fmaxf(m, acc[r][c]);
            const float om = __shfl_xor_sync(0xffffffffu, m, 16);
            m = fmaxf(m, om);
            float s = 0.f;
#pragma unroll
            for (int r = 0; r < 8; r++) {
                ev[r][c] = __expf((acc[r][c] - m) * 0.125f);
                s += ev[r][c];
            }
            s += __shfl_xor_sync(0xffffffffu, s, 16);
#pragma unroll
            for (int r = 0; r < 8; r++) ev[r][c] /= s;
        }
        float ag[4] = {0.f, 0.f, 0.f, 0.f};
#pragma unroll
        for (int r = 0; r < 8; r++) {
            const float4 vv = *(const float4*)(g_xv + (size_t)grow[r] * 64 + n0);
            ag[0] += ev[r][0] * (vv.x + pe[r][0]);
            ag[1] += ev[r][1] * (vv.y + pe[r][1]);
            ag[2] += ev[r][2] * (vv.z + pe[r][2]);
            ag[3] += ev[r][3] * (vv.w + pe[r][3]);
        }
#pragma unroll
        for (int c = 0; c < 4; c++)
            ag[c] += __shfl_xor_sync(0xffffffffu, ag[c], 16);
        if ((ty & 1) == 0) {
            float4 av;
            av.x = tf32r(ag[0]); av.y = tf32r(ag[1]);
            av.z = tf32r(ag[2]); av.w = tf32r(ag[3]);
            ((float4*)(S->agg))[p * 17 + tx] = av;
        }
    }
    __syncthreads();
    stage_w(S->wbuf, Wf, tid);
    __syncthreads();

#pragma unroll
    for (int t2 = 0; t2 < 2; t2++) {
        const int oi = tid + 256 * t2;
        const int pp = oi >> 6;
        const int n  = oi & 63;
        float o = S->bfs[n] + x[(size_t)(pbase + pp) * 64 + n];
        const float* ar = S->agg + pp * 68;
#pragma unroll
        for (int k = 0; k < 64; k++)
            o = fmaf(ar[k], S->wbuf[k * 68 + n], o);
        out[(size_t)(pbase + pp) * 64 + n] = o;
    }
#undef GEMM_PHASE
}

// ============================================================================
// launch
// ============================================================================
extern "C" void kernel_launch(void* const* d_in, const int* in_sizes, int n_in,
                              void* d_out, int out_size) {
    const float* x   = (const float*)d_in[0];
    const float* pos = (const float*)d_in[1];
    const float* Wq  = (const float*)d_in[2];
    const float* Wk  = (const float*)d_in[3];
    const float* Wv  = (const float*)d_in[4];
    const float* P1  = (const float*)d_in[5];
    const float* pb1 = (const float*)d_in[6];
    const float* P2  = (const float*)d_in[7];
    const float* pb2 = (const float*)d_in[8];
    const float* A1  = (const float*)d_in[9];
    const float* ab1 = (const float*)d_in[10];
    const float* A2  = (const float*)d_in[11];
    const float* ab2 = (const float*)d_in[12];
    const float* Wf  = (const float*)d_in[13];
    const float* bf  = (const float*)d_in[14];
    float* out = (float*)d_out;

    cudaFuncSetAttribute(proj_kernel, cudaFuncAttributeMaxDynamicSharedMemorySize,
                         (int)sizeof(ProjSmem));
    cudaFuncSetAttribute(attn_kernel, cudaFuncAttributeMaxDynamicSharedMemorySize,
                         (int)sizeof(AttnSmem));

    knn_kernel<<<2048, 256>>>(pos);
    proj_kernel<<<1024, 1024, sizeof(ProjSmem)>>>(x, Wq, Wk, Wv);
    attn_kernel<<<NPOINTS_TOTAL / PPB, 256, sizeof(AttnSmem)>>>(
        x, pos, P1, pb1, P2, pb2, A1, ab1, A2, ab2, Wf, bf, out);
}

// round 8
// speedup vs baseline: 4.6729x; 1.0098x over previous
#include <cuda_runtime.h>
#include <cuda_bf16.h>
#include <cstddef>
#include <cstdint>

#define BATCH 2
#define NPTS  8192
#define DIM   64
#define KNN   16
#define NPOINTS_TOTAL (BATCH * NPTS)
#define PPB   8    // points per attn block (128 rows)

// tf32 operand rounding for the K=64 GEMMs (cublas tf32 path emulation).
__device__ __forceinline__ float tf32r(float x) {
    uint32_t y;
    asm("cvt.rna.tf32.f32 %0, %1;" : "=r"(y) : "f"(x));
    return __uint_as_float(y);
}

// ---- packed fp32x2 helpers (Blackwell dual-fp32 pipe) ----
__device__ __forceinline__ unsigned long long pk2(float lo, float hi) {
    unsigned long long r;
    asm("mov.b64 %0, {%1, %2};" : "=l"(r) : "f"(lo), "f"(hi));
    return r;
}
__device__ __forceinline__ unsigned long long splat2(float v) {
    unsigned long long r;
    asm("mov.b64 %0, {%1, %1};" : "=l"(r) : "f"(v));
    return r;
}
__device__ __forceinline__ void fma2(unsigned long long& d,
                                     unsigned long long a, unsigned long long b) {
    // two independent fp32 rn-rounded FMAs: bit-identical to scalar fmaf pair
    asm("fma.rn.f32x2 %0, %1, %2, %0;" : "+l"(d) : "l"(a), "l"(b));
}
__device__ __forceinline__ void unpk2(unsigned long long v, float& lo, float& hi) {
    asm("mov.b64 {%0, %1}, %2;" : "=f"(lo), "=f"(hi) : "l"(v));
}

// ---------------- scratch (static device globals; no runtime allocation) ----
__device__ float g_xq[NPOINTS_TOTAL * DIM];
__device__ float g_xk[NPOINTS_TOTAL * DIM];
__device__ float g_xv[NPOINTS_TOTAL * DIM];
__device__ int   g_idx[NPOINTS_TOTAL * KNN];

// ============================================================================
// KNN kernel v3: warp-collective top-16, two candidates per ballot.
// Distance arithmetic + (d2, idx) tie semantics identical to passing R7.
// ============================================================================
__global__ void __launch_bounds__(256) knn_kernel(const float* __restrict__ pos) {
    const int b    = blockIdx.x >> 10;
    const int blk  = blockIdx.x & 1023;
    const int wid  = threadIdx.x >> 5;
    const int lane = threadIdx.x & 31;
    const int n    = blk * 8 + wid;
    const unsigned FULL = 0xffffffffu;

    const float* posb = pos + (size_t)b * NPTS * 3;
    __shared__ float4 tile[1024];

    const float qx = posb[n * 3 + 0];
    const float qy = posb[n * 3 + 1];
    const float qz = posb[n * 3 + 2];
    const float sqq = __fadd_rn(__fadd_rn(__fmul_rn(qx, qx), __fmul_rn(qy, qy)),
                                __fmul_rn(qz, qz));

    float kd = 1e30f;
    int   ki = 0x7fffffff;
    float thr   = 1e30f;
    int   thrid = 0x7fffffff;

    for (int base = 0; base < NPTS; base += 1024) {
        __syncthreads();
        for (int t = threadIdx.x; t < 1024; t += 256) {
            const int j = base + t;
            const float px = posb[j * 3 + 0];
            const float py = posb[j * 3 + 1];
            const float pz = posb[j * 3 + 2];
            const float sq = __fadd_rn(__fadd_rn(__fmul_rn(px, px), __fmul_rn(py, py)),
                                       __fmul_rn(pz, pz));
            tile[t] = make_float4(px, py, pz, sq);
        }
        __syncthreads();

#pragma unroll 2
        for (int it = 0; it < 16; it++) {
            const int t0 = it * 64 + lane;
            const int t1 = t0 + 32;
            const float4 p0 = tile[t0];
            const float4 p1 = tile[t1];
            const float dot0 = __fadd_rn(__fadd_rn(__fmul_rn(qx, p0.x), __fmul_rn(qy, p0.y)),
                                         __fmul_rn(qz, p0.z));
            const float dot1 = __fadd_rn(__fadd_rn(__fmul_rn(qx, p1.x), __fmul_rn(qy, p1.y)),
                                         __fmul_rn(qz, p1.z));
            const float d20 = __fsub_rn(__fadd_rn(sqq, p0.w), __fmul_rn(2.0f, dot0));
            const float d21 = __fsub_rn(__fadd_rn(sqq, p1.w), __fmul_rn(2.0f, dot1));
            const int j0 = base + t0;
            const int j1 = base + t1;

            const bool q0 = (d20 < thr) || (d20 == thr && j0 < thrid);
            const bool q1 = (d21 < thr) || (d21 == thr && j1 < thrid);
            if (__ballot_sync(FULL, q0 || q1)) {
#pragma unroll 1
                for (int half = 0; half < 2; half++) {
                    const float d2 = half ? d21 : d20;
                    const int   j  = half ? j1 : j0;
                    unsigned mask = __ballot_sync(FULL, half ? q1 : q0);
                    while (mask) {
                        const int src = __ffs(mask) - 1;
                        mask &= mask - 1;
                        const float nd = __shfl_sync(FULL, d2, src);
                        const int   nj = __shfl_sync(FULL, j, src);
                        if (nd < thr || (nd == thr && nj < thrid)) {
                            const bool less = (kd < nd) || (kd == nd && ki < nj);
                            const unsigned lm = __ballot_sync(FULL, less && (lane < 16));
                            const int pos = __popc(lm);
                            const float upkd = __shfl_up_sync(FULL, kd, 1);
                            const int   upki = __shfl_up_sync(FULL, ki, 1);
                            if (lane >= pos) {
                                if (lane == pos) { kd = nd; ki = nj; }
                                else             { kd = upkd; ki = upki; }
                            }
                            thr   = __shfl_sync(FULL, kd, 15);
                            thrid = __shfl_sync(FULL, ki, 15);
                        }
                    }
                }
            }
        }
    }

    if (lane < 16) g_idx[((b << 13) + n) * KNN + lane] = ki;
}

// ============================================================================
// Projection kernel (unchanged).
// ============================================================================
struct ProjSmem {
    float WqT[64 * 68];
    float WkT[64 * 68];
    float WvT[64 * 68];
    float xs[16 * 68];
};

__global__ void __launch_bounds__(1024) proj_kernel(const float* __restrict__ x,
                                                    const float* __restrict__ Wq,
                                                    const float* __restrict__ Wk,
                                                    const float* __restrict__ Wv) {
    extern __shared__ __align__(16) unsigned char proj_raw[];
    ProjSmem* S = reinterpret_cast<ProjSmem*>(proj_raw);

    const int tid = threadIdx.x;
    const int r = tid >> 6;
    const int d = tid & 63;

    for (int e = tid; e < 4096; e += 1024) {
        const int i = e >> 6, c = e & 63;
        S->WqT[c * 68 + i] = tf32r(Wq[e]);
        S->WkT[c * 68 + i] = tf32r(Wk[e]);
        S->WvT[c * 68 + i] = tf32r(Wv[e]);
    }
    const size_t rowbase = (size_t)blockIdx.x * 16;
    for (int e = tid; e < 16 * 64; e += 1024) {
        const int rr = e >> 6, c = e & 63;
        S->xs[rr * 68 + c] = tf32r(x[(rowbase + rr) * 64 + c]);
    }
    __syncthreads();

    const float4* xv4 = (const float4*)(S->xs + r * 68);
    const float4* wq4 = (const float4*)(S->WqT + d * 68);
    const float4* wk4 = (const float4*)(S->WkT + d * 68);
    const float4* wv4 = (const float4*)(S->WvT + d * 68);
    float aq = 0.f, ak = 0.f, av = 0.f;
#pragma unroll
    for (int i = 0; i < 16; i++) {
        const float4 xv = xv4[i];
        const float4 wq = wq4[i];
        const float4 wk = wk4[i];
        const float4 wv = wv4[i];
        aq = fmaf(wq.x, xv.x, aq); aq = fmaf(wq.y, xv.y, aq);
        aq = fmaf(wq.z, xv.z, aq); aq = fmaf(wq.w, xv.w, aq);
        ak = fmaf(wk.x, xv.x, ak); ak = fmaf(wk.y, xv.y, ak);
        ak = fmaf(wk.z, xv.z, ak); ak = fmaf(wk.w, xv.w, ak);
        av = fmaf(wv.x, xv.x, av); av = fmaf(wv.y, xv.y, av);
        av = fmaf(wv.z, xv.z, av); av = fmaf(wv.w, xv.w, av);
    }
    const size_t o = (rowbase + r) * 64 + d;
    g_xq[o] = aq; g_xk[o] = ak; g_xv[o] = av;
}

// ============================================================================
// Attention kernel v4: register-blocked GEMM with packed fp32x2 accumulators.
// Same tiling as passing R6/R7; fma.rn.f32x2 is bit-identical to scalar pairs.
// ============================================================================
struct AttnSmem {
    float actA[128 * 68];
    float actB[128 * 68];
    float wbuf[64 * 68];
    float qs[PPB * 68];
    float agg[PPB * 68];
    float rel[128 * 4];
    float P1s[3 * 64];
    float pb1s[64], pb2s[64], ab1s[64], ab2s[64], bfs[64];
};

__device__ __forceinline__ void stage_w(float* __restrict__ dst,
                                        const float* __restrict__ W, int tid) {
    for (int e = tid; e < 4096; e += 256)
        dst[(e >> 6) * 68 + (e & 63)] = tf32r(W[e]);
}

__global__ void __launch_bounds__(256, 2) attn_kernel(
    const float* __restrict__ x,
    const float* __restrict__ pos,
    const float* __restrict__ P1,
    const float* __restrict__ pb1,
    const float* __restrict__ P2,
    const float* __restrict__ pb2,
    const float* __restrict__ A1,
    const float* __restrict__ ab1,
    const float* __restrict__ A2,
    const float* __restrict__ ab2,
    const float* __restrict__ Wf,
    const float* __restrict__ bf,
    float* __restrict__ out) {
    extern __shared__ __align__(16) unsigned char attn_raw[];
    AttnSmem* S = reinterpret_cast<AttnSmem*>(attn_raw);

    const int tid = threadIdx.x;
    const int tx  = tid & 15;
    const int ty  = tid >> 4;
    const int n0  = tx * 4;
    const int m0  = ty * 8;
    const int p   = ty >> 1;
    const int pbase = blockIdx.x * PPB;
    const int b   = pbase >> 13;

    if (tid < 192) S->P1s[tid] = P1[tid];
    if (tid < 64) {
        S->pb1s[tid] = pb1[tid];
        S->pb2s[tid] = pb2[tid];
        S->ab1s[tid] = ab1[tid];
        S->ab2s[tid] = ab2[tid];
        S->bfs[tid]  = bf[tid];
    }
    for (int e = tid; e < PPB * 64; e += 256)
        S->qs[(e >> 6) * 68 + (e & 63)] = g_xq[(size_t)pbase * 64 + e];

    int grow[8];
#pragma unroll
    for (int r = 0; r < 8; r++)
        grow[r] = (b << 13) + g_idx[pbase * KNN + m0 + r];

    for (int e = tid; e < 128 * 3; e += 256) {
        const int m = e / 3, c = e % 3;
        const int pp = m >> 4;
        const int nb = g_idx[pbase * KNN + m];
        S->rel[m * 4 + c] = pos[(size_t)(pbase + pp) * 3 + c]
                          - pos[((size_t)(b << 13) + nb) * 3 + c];
    }
    stage_w(S->wbuf, P2, tid);
    __syncthreads();

    {
        float4* a4 = (float4*)(S->actA);
#pragma unroll
        for (int r = 0; r < 8; r++) {
            const int m = m0 + r;
            const float r0 = S->rel[m * 4 + 0];
            const float r1 = S->rel[m * 4 + 1];
            const float r2 = S->rel[m * 4 + 2];
            float4 hv;
#pragma unroll
            for (int c = 0; c < 4; c++) {
                const int n = n0 + c;
                const float dotp = __fadd_rn(__fadd_rn(__fmul_rn(r0, S->P1s[n]),
                                                       __fmul_rn(r1, S->P1s[64 + n])),
                                             __fmul_rn(r2, S->P1s[128 + n]));
                const float hd = __fadd_rn(dotp, S->pb1s[n]);
                ((float*)&hv)[c] = tf32r(fmaxf(hd, 0.f));
            }
            a4[m * 17 + tx] = hv;
        }
    }
    __syncthreads();

    unsigned long long acc2[8][2];   // packed col pairs (n0+0,n0+1) / (n0+2,n0+3)
    float pe[8][4];
    const ulonglong2* wb2 = (const ulonglong2*)(S->wbuf);

#define ACC_INIT(BIAS)                                                        \
    {                                                                         \
        const unsigned long long b01 = pk2((BIAS)[n0 + 0], (BIAS)[n0 + 1]);   \
        const unsigned long long b23 = pk2((BIAS)[n0 + 2], (BIAS)[n0 + 3]);   \
        _Pragma("unroll")                                                     \
        for (int r = 0; r < 8; r++) { acc2[r][0] = b01; acc2[r][1] = b23; }   \
    }

#define GEMM_PHASE(INBUF)                                                     \
    {                                                                         \
        const float4* in4 = (const float4*)(INBUF);                           \
        _Pragma("unroll 2")                                                   \
        for (int kq = 0; kq < 16; kq++) {                                     \
            const ulonglong2 W0 = wb2[(4 * kq + 0) * 17 + tx];                \
            const ulonglong2 W1 = wb2[(4 * kq + 1) * 17 + tx];                \
            const ulonglong2 W2 = wb2[(4 * kq + 2) * 17 + tx];                \
            const ulonglong2 W3 = wb2[(4 * kq + 3) * 17 + tx];                \
            _Pragma("unroll")                                                 \
            for (int r = 0; r < 8; r++) {                                     \
                const float4 a = in4[(m0 + r) * 17 + kq];                     \
                const unsigned long long ax = splat2(a.x);                    \
                const unsigned long long ay = splat2(a.y);                    \
                const unsigned long long az = splat2(a.z);                    \
                const unsigned long long aw = splat2(a.w);                    \
                fma2(acc2[r][0], ax, W0.x); fma2(acc2[r][1], ax, W0.y);       \
                fma2(acc2[r][0], ay, W1.x); fma2(acc2[r][1], ay, W1.y);       \
                fma2(acc2[r][0], az, W2.x); fma2(acc2[r][1], az, W2.y);       \
                fma2(acc2[r][0], aw, W3.x); fma2(acc2[r][1], aw, W3.y);       \
            }                                                                 \
        }                                                                     \
    }

    // ---- GEMM1: pe = hidden @ P2 + pb2 ; h = q - k + pe -> actB (tf32) ----
    ACC_INIT(S->pb2s);
    GEMM_PHASE(S->actA);
    {
        const float4 qv = ((const float4*)(S->qs))[p * 17 + tx];
        float4* b4 = (float4*)(S->actB);
#pragma unroll
        for (int r = 0; r < 8; r++) {
            unpk2(acc2[r][0], pe[r][0], pe[r][1]);
            unpk2(acc2[r][1], pe[r][2], pe[r][3]);
            const float4 kv = *(const float4*)(g_xk + (size_t)grow[r] * 64 + n0);
            float4 hv;
            hv.x = tf32r(qv.x - kv.x + pe[r][0]);
            hv.y = tf32r(qv.y - kv.y + pe[r][1]);
            hv.z = tf32r(qv.z - kv.z + pe[r][2]);
            hv.w = tf32r(qv.w - kv.w + pe[r][3]);
            b4[(m0 + r) * 17 + tx] = hv;
        }
    }
    __syncthreads();
    stage_w(S->wbuf, A1, tid);
    __syncthreads();

    // ---- GEMM2: t = relu(h @ A1 + ab1) -> actA (tf32) ----
    ACC_INIT(S->ab1s);
    GEMM_PHASE(S->actB);
    {
        float4* a4 = (float4*)(S->actA);
#pragma unroll
        for (int r = 0; r < 8; r++) {
            float t0, t1, t2, t3;
            unpk2(acc2[r][0], t0, t1);
            unpk2(acc2[r][1], t2, t3);
            float4 tv;
            tv.x = tf32r(fmaxf(t0, 0.f));
            tv.y = tf32r(fmaxf(t1, 0.f));
            tv.z = tf32r(fmaxf(t2, 0.f));
            tv.w = tf32r(fmaxf(t3, 0.f));
            a4[(m0 + r) * 17 + tx] = tv;
        }
    }
    __syncthreads();
    stage_w(S->wbuf, A2, tid);
    __syncthreads();

    // ---- GEMM3: a = t @ A2 + ab2 ; softmax ; agg ----
    ACC_INIT(S->ab2s);
    GEMM_PHASE(S->actA);
    {
        float acc[8][4];
#pragma unroll
        for (int r = 0; r < 8; r++) {
            unpk2(acc2[r][0], acc[r][0], acc[r][1]);
            unpk2(acc2[r][1], acc[r][2], acc[r][3]);
        }
        float ev[8][4];
#pragma unroll
        for (int c = 0; c < 4; c++) {
            float m = acc[0][c];
#pragma unroll
            for (int r = 1; r < 8; r++) m = fmaxf(m, acc[r][c]);
            const float om = __shfl_xor_sync(0xffffffffu, m, 16);
            m = fmaxf(m, om);
            float s = 0.f;
#pragma unroll
            for (int r = 0; r < 8; r++) {
                ev[r][c] = __expf((acc[r][c] - m) * 0.125f);
                s += ev[r][c];
            }
            s += __shfl_xor_sync(0xffffffffu, s, 16);
#pragma unroll
            for (int r = 0; r < 8; r++) ev[r][c] /= s;
        }
        float ag[4] = {0.f, 0.f, 0.f, 0.f};
#pragma unroll
        for (int r = 0; r < 8; r++) {
            const float4 vv = *(const float4*)(g_xv + (size_t)grow[r] * 64 + n0);
            ag[0] += ev[r][0] * (vv.x + pe[r][0]);
            ag[1] += ev[r][1] * (vv.y + pe[r][1]);
            ag[2] += ev[r][2] * (vv.z + pe[r][2]);
            ag[3] += ev[r][3] * (vv.w + pe[r][3]);
        }
#pragma unroll
        for (int c = 0; c < 4; c++)
            ag[c] += __shfl_xor_sync(0xffffffffu, ag[c], 16);
        if ((ty & 1) == 0) {
            float4 av;
            av.x = tf32r(ag[0]); av.y = tf32r(ag[1]);
            av.z = tf32r(ag[2]); av.w = tf32r(ag[3]);
            ((float4*)(S->agg))[p * 17 + tx] = av;
        }
    }
    __syncthreads();
    stage_w(S->wbuf, Wf, tid);
    __syncthreads();

    // ---- out = agg @ Wf + bf + x ----
#pragma unroll
    for (int t2 = 0; t2 < 2; t2++) {
        const int oi = tid + 256 * t2;
        const int pp = oi >> 6;
        const int n  = oi & 63;
        float o = S->bfs[n] + x[(size_t)(pbase + pp) * 64 + n];
        const float* ar = S->agg + pp * 68;
#pragma unroll
        for (int k = 0; k < 64; k++)
            o = fmaf(ar[k], S->wbuf[k * 68 + n], o);
        out[(size_t)(pbase + pp) * 64 + n] = o;
    }
#undef GEMM_PHASE
#undef ACC_INIT
}

// ============================================================================
// launch
// ============================================================================
extern "C" void kernel_launch(void* const* d_in, const int* in_sizes, int n_in,
                              void* d_out, int out_size) {
    const float* x   = (const float*)d_in[0];
    const float* pos = (const float*)d_in[1];
    const float* Wq  = (const float*)d_in[2];
    const float* Wk  = (const float*)d_in[3];
    const float* Wv  = (const float*)d_in[4];
    const float* P1  = (const float*)d_in[5];
    const float* pb1 = (const float*)d_in[6];
    const float* P2  = (const float*)d_in[7];
    const float* pb2 = (const float*)d_in[8];
    const float* A1  = (const float*)d_in[9];
    const float* ab1 = (const float*)d_in[10];
    const float* A2  = (const float*)d_in[11];
    const float* ab2 = (const float*)d_in[12];
    const float* Wf  = (const float*)d_in[13];
    const float* bf  = (const float*)d_in[14];
    float* out = (float*)d_out;

    cudaFuncSetAttribute(proj_kernel, cudaFuncAttributeMaxDynamicSharedMemorySize,
                         (int)sizeof(ProjSmem));
    cudaFuncSetAttribute(attn_kernel, cudaFuncAttributeMaxDynamicSharedMemorySize,
                         (int)sizeof(AttnSmem));

    knn_kernel<<<2048, 256>>>(pos);
    proj_kernel<<<1024, 1024, sizeof(ProjSmem)>>>(x, Wq, Wk, Wv);
    attn_kernel<<<NPOINTS_TOTAL / PPB, 256, sizeof(AttnSmem)>>>(
        x, pos, P1, pb1, P2, pb2, A1, ab1, A2, ab2, Wf, bf, out);
}

// round 9
// speedup vs baseline: 5.0500x; 1.0807x over previous
#include <cuda_runtime.h>
#include <cuda_bf16.h>
#include <cstddef>
#include <cstdint>

#define BATCH 2
#define NPTS  8192
#define DIM   64
#define KNN   16
#define NPOINTS_TOTAL (BATCH * NPTS)
#define PPB   8    // points per attn block (128 rows)

// tf32 operand rounding for the K=64 GEMMs (cublas tf32 path emulation).
__device__ __forceinline__ float tf32r(float x) {
    uint32_t y;
    asm("cvt.rna.tf32.f32 %0, %1;" : "=r"(y) : "f"(x));
    return __uint_as_float(y);
}

// ---- packed fp32x2 helpers (Blackwell dual-fp32 pipe) ----
__device__ __forceinline__ unsigned long long pk2(float lo, float hi) {
    unsigned long long r;
    asm("mov.b64 %0, {%1, %2};" : "=l"(r) : "f"(lo), "f"(hi));
    return r;
}
__device__ __forceinline__ unsigned long long splat2(float v) {
    unsigned long long r;
    asm("mov.b64 %0, {%1, %1};" : "=l"(r) : "f"(v));
    return r;
}
__device__ __forceinline__ void fma2(unsigned long long& d,
                                     unsigned long long a, unsigned long long b) {
    asm("fma.rn.f32x2 %0, %1, %2, %0;" : "+l"(d) : "l"(a), "l"(b));
}
__device__ __forceinline__ void unpk2(unsigned long long v, float& lo, float& hi) {
    asm("mov.b64 {%0, %1}, %2;" : "=f"(lo), "=f"(hi) : "l"(v));
}

// ---------------- scratch (static device globals; no runtime allocation) ----
__device__ float g_xq[NPOINTS_TOTAL * DIM];
__device__ float g_xk[NPOINTS_TOTAL * DIM];
__device__ float g_xv[NPOINTS_TOTAL * DIM];
__device__ int   g_idx[NPOINTS_TOTAL * KNN];

// ============================================================================
// KNN kernel v4: warp-collective top-16 with 4-candidate batched threshold.
// Common path: 4 distances -> min4 -> ONE compare+ballot. Trigger path does
// the exact per-candidate (d2, idx) lexicographic qual + insert (== R7).
// Distance arithmetic bit-identical to the passing kernels.
// ============================================================================
__global__ void __launch_bounds__(256) knn_kernel(const float* __restrict__ pos) {
    const int b    = blockIdx.x >> 10;
    const int blk  = blockIdx.x & 1023;
    const int wid  = threadIdx.x >> 5;
    const int lane = threadIdx.x & 31;
    const int n    = blk * 8 + wid;
    const unsigned FULL = 0xffffffffu;

    const float* posb = pos + (size_t)b * NPTS * 3;
    __shared__ float4 tile[1024];

    const float qx = posb[n * 3 + 0];
    const float qy = posb[n * 3 + 1];
    const float qz = posb[n * 3 + 2];
    const float sqq = __fadd_rn(__fadd_rn(__fmul_rn(qx, qx), __fmul_rn(qy, qy)),
                                __fmul_rn(qz, qz));

    float kd = 1e30f;
    int   ki = 0x7fffffff;
    float thr   = 1e30f;
    int   thrid = 0x7fffffff;

    for (int base = 0; base < NPTS; base += 1024) {
        __syncthreads();
        for (int t = threadIdx.x; t < 1024; t += 256) {
            const int j = base + t;
            const float px = posb[j * 3 + 0];
            const float py = posb[j * 3 + 1];
            const float pz = posb[j * 3 + 2];
            const float sq = __fadd_rn(__fadd_rn(__fmul_rn(px, px), __fmul_rn(py, py)),
                                       __fmul_rn(pz, pz));
            tile[t] = make_float4(px, py, pz, sq);
        }
        __syncthreads();

#pragma unroll 2
        for (int it = 0; it < 8; it++) {
            const int t = it * 128 + lane;
            const float4 p0 = tile[t];
            const float4 p1 = tile[t + 32];
            const float4 p2 = tile[t + 64];
            const float4 p3 = tile[t + 96];
            const float dot0 = __fadd_rn(__fadd_rn(__fmul_rn(qx, p0.x), __fmul_rn(qy, p0.y)), __fmul_rn(qz, p0.z));
            const float dot1 = __fadd_rn(__fadd_rn(__fmul_rn(qx, p1.x), __fmul_rn(qy, p1.y)), __fmul_rn(qz, p1.z));
            const float dot2 = __fadd_rn(__fadd_rn(__fmul_rn(qx, p2.x), __fmul_rn(qy, p2.y)), __fmul_rn(qz, p2.z));
            const float dot3 = __fadd_rn(__fadd_rn(__fmul_rn(qx, p3.x), __fmul_rn(qy, p3.y)), __fmul_rn(qz, p3.z));
            const float d2_0 = __fsub_rn(__fadd_rn(sqq, p0.w), __fmul_rn(2.0f, dot0));
            const float d2_1 = __fsub_rn(__fadd_rn(sqq, p1.w), __fmul_rn(2.0f, dot1));
            const float d2_2 = __fsub_rn(__fadd_rn(sqq, p2.w), __fmul_rn(2.0f, dot2));
            const float d2_3 = __fsub_rn(__fadd_rn(sqq, p3.w), __fmul_rn(2.0f, dot3));

            const float dmin = fminf(fminf(d2_0, d2_1), fminf(d2_2, d2_3));
            if (__ballot_sync(FULL, dmin <= thr)) {
#pragma unroll
                for (int c = 0; c < 4; c++) {
                    const float d2 = (c == 0) ? d2_0 : (c == 1) ? d2_1 : (c == 2) ? d2_2 : d2_3;
                    const int   j  = base + t + 32 * c;
                    const bool qual = (d2 < thr) || (d2 == thr && j < thrid);
                    unsigned mask = __ballot_sync(FULL, qual);
                    while (mask) {
                        const int src = __ffs(mask) - 1;
                        mask &= mask - 1;
                        const float nd = __shfl_sync(FULL, d2, src);
                        const int   nj = __shfl_sync(FULL, j, src);
                        if (nd < thr || (nd == thr && nj < thrid)) {
                            const bool less = (kd < nd) || (kd == nd && ki < nj);
                            const unsigned lm = __ballot_sync(FULL, less && (lane < 16));
                            const int pos = __popc(lm);
                            const float upkd = __shfl_up_sync(FULL, kd, 1);
                            const int   upki = __shfl_up_sync(FULL, ki, 1);
                            if (lane >= pos) {
                                if (lane == pos) { kd = nd; ki = nj; }
                                else             { kd = upkd; ki = upki; }
                            }
                            thr   = __shfl_sync(FULL, kd, 15);
                            thrid = __shfl_sync(FULL, ki, 15);
                        }
                    }
                }
            }
        }
    }

    if (lane < 16) g_idx[((b << 13) + n) * KNN + lane] = ki;
}

// ============================================================================
// Projection kernel (unchanged).
// ============================================================================
struct ProjSmem {
    float WqT[64 * 68];
    float WkT[64 * 68];
    float WvT[64 * 68];
    float xs[16 * 68];
};

__global__ void __launch_bounds__(1024) proj_kernel(const float* __restrict__ x,
                                                    const float* __restrict__ Wq,
                                                    const float* __restrict__ Wk,
                                                    const float* __restrict__ Wv) {
    extern __shared__ __align__(16) unsigned char proj_raw[];
    ProjSmem* S = reinterpret_cast<ProjSmem*>(proj_raw);

    const int tid = threadIdx.x;
    const int r = tid >> 6;
    const int d = tid & 63;

    for (int e = tid; e < 4096; e += 1024) {
        const int i = e >> 6, c = e & 63;
        S->WqT[c * 68 + i] = tf32r(Wq[e]);
        S->WkT[c * 68 + i] = tf32r(Wk[e]);
        S->WvT[c * 68 + i] = tf32r(Wv[e]);
    }
    const size_t rowbase = (size_t)blockIdx.x * 16;
    for (int e = tid; e < 16 * 64; e += 1024) {
        const int rr = e >> 6, c = e & 63;
        S->xs[rr * 68 + c] = tf32r(x[(rowbase + rr) * 64 + c]);
    }
    __syncthreads();

    const float4* xv4 = (const float4*)(S->xs + r * 68);
    const float4* wq4 = (const float4*)(S->WqT + d * 68);
    const float4* wk4 = (const float4*)(S->WkT + d * 68);
    const float4* wv4 = (const float4*)(S->WvT + d * 68);
    float aq = 0.f, ak = 0.f, av = 0.f;
#pragma unroll
    for (int i = 0; i < 16; i++) {
        const float4 xv = xv4[i];
        const float4 wq = wq4[i];
        const float4 wk = wk4[i];
        const float4 wv = wv4[i];
        aq = fmaf(wq.x, xv.x, aq); aq = fmaf(wq.y, xv.y, aq);
        aq = fmaf(wq.z, xv.z, aq); aq = fmaf(wq.w, xv.w, aq);
        ak = fmaf(wk.x, xv.x, ak); ak = fmaf(wk.y, xv.y, ak);
        ak = fmaf(wk.z, xv.z, ak); ak = fmaf(wk.w, xv.w, ak);
        av = fmaf(wv.x, xv.x, av); av = fmaf(wv.y, xv.y, av);
        av = fmaf(wv.z, xv.z, av); av = fmaf(wv.w, xv.w, av);
    }
    const size_t o = (rowbase + r) * 64 + d;
    g_xq[o] = aq; g_xk[o] = ak; g_xv[o] = av;
}

// ============================================================================
// Attention kernel v4 (unchanged from passing R8): fp32x2 register-blocked GEMM.
// ============================================================================
struct AttnSmem {
    float actA[128 * 68];
    float actB[128 * 68];
    float wbuf[64 * 68];
    float qs[PPB * 68];
    float agg[PPB * 68];
    float rel[128 * 4];
    float P1s[3 * 64];
    float pb1s[64], pb2s[64], ab1s[64], ab2s[64], bfs[64];
};

__device__ __forceinline__ void stage_w(float* __restrict__ dst,
                                        const float* __restrict__ W, int tid) {
    for (int e = tid; e < 4096; e += 256)
        dst[(e >> 6) * 68 + (e & 63)] = tf32r(W[e]);
}

__global__ void __launch_bounds__(256, 2) attn_kernel(
    const float* __restrict__ x,
    const float* __restrict__ pos,
    const float* __restrict__ P1,
    const float* __restrict__ pb1,
    const float* __restrict__ P2,
    const float* __restrict__ pb2,
    const float* __restrict__ A1,
    const float* __restrict__ ab1,
    const float* __restrict__ A2,
    const float* __restrict__ ab2,
    const float* __restrict__ Wf,
    const float* __restrict__ bf,
    float* __restrict__ out) {
    extern __shared__ __align__(16) unsigned char attn_raw[];
    AttnSmem* S = reinterpret_cast<AttnSmem*>(attn_raw);

    const int tid = threadIdx.x;
    const int tx  = tid & 15;
    const int ty  = tid >> 4;
    const int n0  = tx * 4;
    const int m0  = ty * 8;
    const int p   = ty >> 1;
    const int pbase = blockIdx.x * PPB;
    const int b   = pbase >> 13;

    if (tid < 192) S->P1s[tid] = P1[tid];
    if (tid < 64) {
        S->pb1s[tid] = pb1[tid];
        S->pb2s[tid] = pb2[tid];
        S->ab1s[tid] = ab1[tid];
        S->ab2s[tid] = ab2[tid];
        S->bfs[tid]  = bf[tid];
    }
    for (int e = tid; e < PPB * 64; e += 256)
        S->qs[(e >> 6) * 68 + (e & 63)] = g_xq[(size_t)pbase * 64 + e];

    int grow[8];
#pragma unroll
    for (int r = 0; r < 8; r++)
        grow[r] = (b << 13) + g_idx[pbase * KNN + m0 + r];

    for (int e = tid; e < 128 * 3; e += 256) {
        const int m = e / 3, c = e % 3;
        const int pp = m >> 4;
        const int nb = g_idx[pbase * KNN + m];
        S->rel[m * 4 + c] = pos[(size_t)(pbase + pp) * 3 + c]
                          - pos[((size_t)(b << 13) + nb) * 3 + c];
    }
    stage_w(S->wbuf, P2, tid);
    __syncthreads();

    {
        float4* a4 = (float4*)(S->actA);
#pragma unroll
        for (int r = 0; r < 8; r++) {
            const int m = m0 + r;
            const float r0 = S->rel[m * 4 + 0];
            const float r1 = S->rel[m * 4 + 1];
            const float r2 = S->rel[m * 4 + 2];
            float4 hv;
#pragma unroll
            for (int c = 0; c < 4; c++) {
                const int n = n0 + c;
                const float dotp = __fadd_rn(__fadd_rn(__fmul_rn(r0, S->P1s[n]),
                                                       __fmul_rn(r1, S->P1s[64 + n])),
                                             __fmul_rn(r2, S->P1s[128 + n]));
                const float hd = __fadd_rn(dotp, S->pb1s[n]);
                ((float*)&hv)[c] = tf32r(fmaxf(hd, 0.f));
            }
            a4[m * 17 + tx] = hv;
        }
    }
    __syncthreads();

    unsigned long long acc2[8][2];
    float pe[8][4];
    const ulonglong2* wb2 = (const ulonglong2*)(S->wbuf);

#define ACC_INIT(BIAS)                                                        \
    {                                                                         \
        const unsigned long long b01 = pk2((BIAS)[n0 + 0], (BIAS)[n0 + 1]);   \
        const unsigned long long b23 = pk2((BIAS)[n0 + 2], (BIAS)[n0 + 3]);   \
        _Pragma("unroll")                                                     \
        for (int r = 0; r < 8; r++) { acc2[r][0] = b01; acc2[r][1] = b23; }   \
    }

#define GEMM_PHASE(INBUF)                                                     \
    {                                                                         \
        const float4* in4 = (const float4*)(INBUF);                           \
        _Pragma("unroll 2")                                                   \
        for (int kq = 0; kq < 16; kq++) {                                     \
            const ulonglong2 W0 = wb2[(4 * kq + 0) * 17 + tx];                \
            const ulonglong2 W1 = wb2[(4 * kq + 1) * 17 + tx];                \
            const ulonglong2 W2 = wb2[(4 * kq + 2) * 17 + tx];                \
            const ulonglong2 W3 = wb2[(4 * kq + 3) * 17 + tx];                \
            _Pragma("unroll")                                                 \
            for (int r = 0; r < 8; r++) {                                     \
                const float4 a = in4[(m0 + r) * 17 + kq];                     \
                const unsigned long long ax = splat2(a.x);                    \
                const unsigned long long ay = splat2(a.y);                    \
                const unsigned long long az = splat2(a.z);                    \
                const unsigned long long aw = splat2(a.w);                    \
                fma2(acc2[r][0], ax, W0.x); fma2(acc2[r][1], ax, W0.y);       \
                fma2(acc2[r][0], ay, W1.x); fma2(acc2[r][1], ay, W1.y);       \
                fma2(acc2[r][0], az, W2.x); fma2(acc2[r][1], az, W2.y);       \
                fma2(acc2[r][0], aw, W3.x); fma2(acc2[r][1], aw, W3.y);       \
            }                                                                 \
        }                                                                     \
    }

    ACC_INIT(S->pb2s);
    GEMM_PHASE(S->actA);
    {
        const float4 qv = ((const float4*)(S->qs))[p * 17 + tx];
        float4* b4 = (float4*)(S->actB);
#pragma unroll
        for (int r = 0; r < 8; r++) {
            unpk2(acc2[r][0], pe[r][0], pe[r][1]);
            unpk2(acc2[r][1], pe[r][2], pe[r][3]);
            const float4 kv = *(const float4*)(g_xk + (size_t)grow[r] * 64 + n0);
            float4 hv;
            hv.x = tf32r(qv.x - kv.x + pe[r][0]);
            hv.y = tf32r(qv.y - kv.y + pe[r][1]);
            hv.z = tf32r(qv.z - kv.z + pe[r][2]);
            hv.w = tf32r(qv.w - kv.w + pe[r][3]);
            b4[(m0 + r) * 17 + tx] = hv;
        }
    }
    __syncthreads();
    stage_w(S->wbuf, A1, tid);
    __syncthreads();

    ACC_INIT(S->ab1s);
    GEMM_PHASE(S->actB);
    {
        float4* a4 = (float4*)(S->actA);
#pragma unroll
        for (int r = 0; r < 8; r++) {
            float t0, t1, t2, t3;
            unpk2(acc2[r][0], t0, t1);
            unpk2(acc2[r][1], t2, t3);
            float4 tv;
            tv.x = tf32r(fmaxf(t0, 0.f));
            tv.y = tf32r(fmaxf(t1, 0.f));
            tv.z = tf32r(fmaxf(t2, 0.f));
            tv.w = tf32r(fmaxf(t3, 0.f));
            a4[(m0 + r) * 17 + tx] = tv;
        }
    }
    __syncthreads();
    stage_w(S->wbuf, A2, tid);
    __syncthreads();

    ACC_INIT(S->ab2s);
    GEMM_PHASE(S->actA);
    {
        float acc[8][4];
#pragma unroll
        for (int r = 0; r < 8; r++) {
            unpk2(acc2[r][0], acc[r][0], acc[r][1]);
            unpk2(acc2[r][1], acc[r][2], acc[r][3]);
        }
        float ev[8][4];
#pragma unroll
        for (int c = 0; c < 4; c++) {
            float m = acc[0][c];
#pragma unroll
            for (int r = 1; r < 8; r++) m = fmaxf(m, acc[r][c]);
            const float om = __shfl_xor_sync(0xffffffffu, m, 16);
            m = fmaxf(m, om);
            float s = 0.f;
#pragma unroll
            for (int r = 0; r < 8; r++) {
                ev[r][c] = __expf((acc[r][c] - m) * 0.125f);
                s += ev[r][c];
            }
            s += __shfl_xor_sync(0xffffffffu, s, 16);
#pragma unroll
            for (int r = 0; r < 8; r++) ev[r][c] /= s;
        }
        float ag[4] = {0.f, 0.f, 0.f, 0.f};
#pragma unroll
        for (int r = 0; r < 8; r++) {
            const float4 vv = *(const float4*)(g_xv + (size_t)grow[r] * 64 + n0);
            ag[0] += ev[r][0] * (vv.x + pe[r][0]);
            ag[1] += ev[r][1] * (vv.y + pe[r][1]);
            ag[2] += ev[r][2] * (vv.z + pe[r][2]);
            ag[3] += ev[r][3] * (vv.w + pe[r][3]);
        }
#pragma unroll
        for (int c = 0; c < 4; c++)
            ag[c] += __shfl_xor_sync(0xffffffffu, ag[c], 16);
        if ((ty & 1) == 0) {
            float4 av;
            av.x = tf32r(ag[0]); av.y = tf32r(ag[1]);
            av.z = tf32r(ag[2]); av.w = tf32r(ag[3]);
            ((float4*)(S->agg))[p * 17 + tx] = av;
        }
    }
    __syncthreads();
    stage_w(S->wbuf, Wf, tid);
    __syncthreads();

#pragma unroll
    for (int t2 = 0; t2 < 2; t2++) {
        const int oi = tid + 256 * t2;
        const int pp = oi >> 6;
        const int n  = oi & 63;
        float o = S->bfs[n] + x[(size_t)(pbase + pp) * 64 + n];
        const float* ar = S->agg + pp * 68;
#pragma unroll
        for (int k = 0; k < 64; k++)
            o = fmaf(ar[k], S->wbuf[k * 68 + n], o);
        out[(size_t)(pbase + pp) * 64 + n] = o;
    }
#undef GEMM_PHASE
#undef ACC_INIT
}

// ============================================================================
// launch
// ============================================================================
extern "C" void kernel_launch(void* const* d_in, const int* in_sizes, int n_in,
                              void* d_out, int out_size) {
    const float* x   = (const float*)d_in[0];
    const float* pos = (const float*)d_in[1];
    const float* Wq  = (const float*)d_in[2];
    const float* Wk  = (const float*)d_in[3];
    const float* Wv  = (const float*)d_in[4];
    const float* P1  = (const float*)d_in[5];
    const float* pb1 = (const float*)d_in[6];
    const float* P2  = (const float*)d_in[7];
    const float* pb2 = (const float*)d_in[8];
    const float* A1  = (const float*)d_in[9];
    const float* ab1 = (const float*)d_in[10];
    const float* A2  = (const float*)d_in[11];
    const float* ab2 = (const float*)d_in[12];
    const float* Wf  = (const float*)d_in[13];
    const float* bf  = (const float*)d_in[14];
    float* out = (float*)d_out;

    cudaFuncSetAttribute(proj_kernel, cudaFuncAttributeMaxDynamicSharedMemorySize,
                         (int)sizeof(ProjSmem));
    cudaFuncSetAttribute(attn_kernel, cudaFuncAttributeMaxDynamicSharedMemorySize,
                         (int)sizeof(AttnSmem));

    knn_kernel<<<2048, 256>>>(pos);
    proj_kernel<<<1024, 1024, sizeof(ProjSmem)>>>(x, Wq, Wk, Wv);
    attn_kernel<<<NPOINTS_TOTAL / PPB, 256, sizeof(AttnSmem)>>>(
        x, pos, P1, pb1, P2, pb2, A1, ab1, A2, ab2, Wf, bf, out);
}